// round 12
// baseline (speedup 1.0000x reference)
#include <cuda_runtime.h>
#include <cuda_bf16.h>
#include <cstdint>
#include <math.h>

#define BB 4
#define LL 2048
#define DD 1024
#define HH 16
#define DKK 64
#define BH (BB*HH)
#define MROWS (BB*LL)

#define SPAD 40
#define SPAD2 72

#define ST_AH 0
#define ST_AL 10240
#define ST_BH 20480
#define ST_BL 25600
#define STAGE_BYTES 30720
#define PROJ_SMEM (3*STAGE_BYTES)
#define PIPE_SMEM (2*STAGE_BYTES)

#define SC_QH 0
#define SC_QL 18432
#define SC_KH 36864
#define SC_KL 55296
#define SC_SMEM 73728

typedef unsigned short u16;

__device__ u16 g_xh[(size_t)MROWS * DD], g_xl[(size_t)MROWS * DD];
__device__ u16 g_wh[(size_t)4 * DD * DD], g_wl[(size_t)4 * DD * DD];
__device__ u16 g_och[(size_t)MROWS * DD], g_ocl[(size_t)MROWS * DD];
__device__ float g_q[(size_t)BH * LL * DKK];
__device__ float g_k[(size_t)BH * LL * DKK];
__device__ float g_vt[(size_t)BH * DKK * LL];
__device__ float g_oc[(size_t)MROWS * DD];
__device__ float g_attn_scratch[(size_t)BH * LL * LL];

__device__ __forceinline__ uint32_t s32(const void* p) {
    return (uint32_t)__cvta_generic_to_shared(p);
}

#define LDSM_X4(R, a)                                                          \
    asm volatile("ldmatrix.sync.aligned.m8n8.x4.shared.b16 {%0,%1,%2,%3}, [%4];" \
        : "=r"((R)[0]), "=r"((R)[1]), "=r"((R)[2]), "=r"((R)[3]) : "r"(a))
#define LDSM_X2(R, a)                                                          \
    asm volatile("ldmatrix.sync.aligned.m8n8.x2.shared.b16 {%0,%1}, [%2];"     \
        : "=r"((R)[0]), "=r"((R)[1]) : "r"(a))

#define CP16(dst, src) \
    asm volatile("cp.async.cg.shared.global [%0], [%1], 16;" :: "r"(dst), "l"(src) : "memory")
#define CP_COMMIT()  asm volatile("cp.async.commit_group;" ::: "memory")
#define CP_WAIT2()   asm volatile("cp.async.wait_group 2;" ::: "memory")
#define CP_WAIT0()   asm volatile("cp.async.wait_group 0;" ::: "memory")

__device__ __forceinline__ void mma_bf16(float* c, const uint32_t* a, const uint32_t* b) {
    asm volatile(
        "mma.sync.aligned.m16n8k16.row.col.f32.bf16.bf16.f32 "
        "{%0,%1,%2,%3}, {%4,%5,%6,%7}, {%8,%9}, {%0,%1,%2,%3};"
        : "+f"(c[0]), "+f"(c[1]), "+f"(c[2]), "+f"(c[3])
        : "r"(a[0]), "r"(a[1]), "r"(a[2]), "r"(a[3]), "r"(b[0]), "r"(b[1]));
}

__device__ __forceinline__ void cvt_split(const float4& v, uint2& hv, uint2& lv) {
    __nv_bfloat16 h0 = __float2bfloat16(v.x), h1 = __float2bfloat16(v.y);
    __nv_bfloat16 h2 = __float2bfloat16(v.z), h3 = __float2bfloat16(v.w);
    __nv_bfloat16 l0 = __float2bfloat16(v.x - __bfloat162float(h0));
    __nv_bfloat16 l1 = __float2bfloat16(v.y - __bfloat162float(h1));
    __nv_bfloat16 l2 = __float2bfloat16(v.z - __bfloat162float(h2));
    __nv_bfloat16 l3 = __float2bfloat16(v.w - __bfloat162float(h3));
    hv.x = ((uint32_t)__bfloat16_as_ushort(h1) << 16) | __bfloat16_as_ushort(h0);
    hv.y = ((uint32_t)__bfloat16_as_ushort(h3) << 16) | __bfloat16_as_ushort(h2);
    lv.x = ((uint32_t)__bfloat16_as_ushort(l1) << 16) | __bfloat16_as_ushort(l0);
    lv.y = ((uint32_t)__bfloat16_as_ushort(l3) << 16) | __bfloat16_as_ushort(l2);
}

#define XU (MROWS * DD / 4)
#define WU (DD * DD / 4)
__global__ void split_all(const float* __restrict__ x,
                          const float* __restrict__ wq, const float* __restrict__ wk,
                          const float* __restrict__ wv, const float* __restrict__ wo,
                          u16* __restrict__ xh, u16* __restrict__ xl,
                          u16* __restrict__ wh, u16* __restrict__ wl) {
    const int i = blockIdx.x * 256 + threadIdx.x;
    const float* src; u16 *dh, *dl; size_t off;
    if (i < XU) {
        src = x; off = i; dh = xh; dl = xl;
    } else {
        const int wi = (i - XU) / WU;
        off = (size_t)((i - XU) % WU);
        src = (wi == 0) ? wq : (wi == 1) ? wk : (wi == 2) ? wv : wo;
        dh = wh + (size_t)wi * DD * DD;
        dl = wl + (size_t)wi * DD * DD;
    }
    float4 v = ((const float4*)src)[off];
    uint2 h, l; cvt_split(v, h, l);
    ((uint2*)dh)[off] = h;
    ((uint2*)dl)[off] = l;
}

__global__ void split_oc(const float* __restrict__ src, u16* __restrict__ hi,
                         u16* __restrict__ lo) {
    const int i = blockIdx.x * 256 + threadIdx.x;
    float4 v = ((const float4*)src)[i];
    uint2 h, l; cvt_split(v, h, l);
    ((uint2*)hi)[i] = h;
    ((uint2*)lo)[i] = l;
}

template <int N4>
__device__ __forceinline__ void ldg_chunk(float4 (&r)[N4], const float* __restrict__ g,
                                          int ld, int tid) {
    #pragma unroll
    for (int i = 0; i < N4; i++) {
        const int u = tid + i * 256;
        const int row = u >> 3, c4 = (u & 7) << 2;
        r[i] = *(const float4*)(g + (size_t)row * ld + c4);
    }
}
template <int N4>
__device__ __forceinline__ void sts_chunk(const float4 (&v)[N4], u16* shi,
                                          u16* slo, int tid) {
    #pragma unroll
    for (int i = 0; i < N4; i++) {
        const int u = tid + i * 256;
        const int row = u >> 3, c4 = (u & 7) << 2;
        uint2 hv, lv; cvt_split(v[i], hv, lv);
        *(uint2*)(shi + row * SPAD + c4) = hv;
        *(uint2*)(slo + row * SPAD + c4) = lv;
    }
}

__device__ __forceinline__ void load_split64(u16* shi, u16* slo,
                                             const float* __restrict__ g, int ld, int tid) {
    #pragma unroll
    for (int i = 0; i < 8; i++) {
        const int u = tid + i * 256;
        const int r = u >> 4, c4 = (u & 15) << 2;
        float4 v = *(const float4*)(g + (size_t)r * ld + c4);
        uint2 hv, lv; cvt_split(v, hv, lv);
        *(uint2*)(shi + r * SPAD2 + c4) = hv;
        *(uint2*)(slo + r * SPAD2 + c4) = lv;
    }
}

__device__ __forceinline__ void ldg_k(float4 (&r)[8], const float* __restrict__ g, int tid) {
    #pragma unroll
    for (int i = 0; i < 8; i++) {
        const int u = tid + i * 256;
        r[i] = *(const float4*)(g + (size_t)(u >> 4) * DKK + ((u & 15) << 2));
    }
}
__device__ __forceinline__ void sts_k(const float4 (&v)[8], char* hi, char* lo, int tid) {
    #pragma unroll
    for (int i = 0; i < 8; i++) {
        const int u = tid + i * 256;
        const int r = u >> 4, c4 = (u & 15) << 2;
        uint2 hv, lv; cvt_split(v[i], hv, lv);
        *(uint2*)((u16*)hi + r * SPAD2 + c4) = hv;
        *(uint2*)((u16*)lo + r * SPAD2 + c4) = lv;
    }
}

template <int MT, int NT, int STRIDE, int KC>
__device__ __forceinline__ void block_mma(
    const u16* sAh, const u16* sAl, const u16* sBh, const u16* sBl,
    int a_row0, int b_row0, int lane, float (&acc)[MT][NT][4]) {
    #pragma unroll
    for (int kb = 0; kb < KC; kb += 16) {
        uint32_t ah[MT][4], al[MT][4], bh[NT][2], bl[NT][2];
        const int ar = a_row0 + (lane & 15);
        const int ac = kb + ((lane >> 4) << 3);
        #pragma unroll
        for (int i = 0; i < MT; i++) {
            LDSM_X4(ah[i], s32(sAh + (ar + i * 16) * STRIDE + ac));
            LDSM_X4(al[i], s32(sAl + (ar + i * 16) * STRIDE + ac));
        }
        const int br = b_row0 + (lane & 7);
        const int bc = kb + (((lane >> 3) & 1) << 3);
        #pragma unroll
        for (int j = 0; j < NT; j++) {
            LDSM_X2(bh[j], s32(sBh + (br + j * 8) * STRIDE + bc));
            LDSM_X2(bl[j], s32(sBl + (br + j * 8) * STRIDE + bc));
        }
        #pragma unroll
        for (int i = 0; i < MT; i++)
            #pragma unroll
            for (int j = 0; j < NT; j++) {
                mma_bf16(acc[i][j], ah[i], bh[j]);
                mma_bf16(acc[i][j], ah[i], bl[j]);
                mma_bf16(acc[i][j], al[i], bh[j]);
            }
    }
}

template <int MT, int NT>
__device__ __forceinline__ void stage_group(float* stg, int warp_m, int col_base, int lane,
                                            float (&acc)[MT][NT][4]) {
    const int r0 = warp_m * MT * 16 + (lane >> 2);
    const int c0 = (lane & 3) * 2;
    #pragma unroll
    for (int i = 0; i < MT; i++)
        #pragma unroll
        for (int j = 0; j < NT; j++) {
            float* p = stg + (size_t)(r0 + i * 16) * 33 + col_base + j * 8 + c0;
            p[0] = acc[i][j][0];
            p[1] = acc[i][j][1];
            p[8 * 33 + 0] = acc[i][j][2];
            p[8 * 33 + 1] = acc[i][j][3];
        }
}

template <int MODE>
__global__ void __launch_bounds__(256, 2)
gemm_proj(const u16* __restrict__ Ah, const u16* __restrict__ Al,
          const u16* __restrict__ Bh, const u16* __restrict__ Bl,
          const float* __restrict__ bias, float* __restrict__ out) {
    extern __shared__ char sm[];
    const int tid = threadIdx.x, lane = tid & 31, wid = tid >> 5;
    const int warp_m = wid & 1, warp_n = wid >> 1;
    const int m0 = blockIdx.y * 128, n0 = blockIdx.x * 64;

    const u16* Ahb = Ah + (size_t)m0 * DD;
    const u16* Alb = Al + (size_t)m0 * DD;
    const u16* Bhb = Bh + (size_t)n0 * DD;
    const u16* Blb = Bl + (size_t)n0 * DD;

    const int a_row = tid >> 2, a_c8 = (tid & 3) << 3;

    #define PROJ_ISSUE(k, stg) do {                                                        \
        const int _k0 = (k) * 32;                                                          \
        CP16(s32(stg) + ST_AH + (a_row * SPAD + a_c8) * 2,                                 \
             Ahb + (size_t)a_row * DD + _k0 + a_c8);                                       \
        CP16(s32(stg) + ST_AH + ((a_row + 64) * SPAD + a_c8) * 2,                          \
             Ahb + (size_t)(a_row + 64) * DD + _k0 + a_c8);                                \
        CP16(s32(stg) + ST_AL + (a_row * SPAD + a_c8) * 2,                                 \
             Alb + (size_t)a_row * DD + _k0 + a_c8);                                       \
        CP16(s32(stg) + ST_AL + ((a_row + 64) * SPAD + a_c8) * 2,                          \
             Alb + (size_t)(a_row + 64) * DD + _k0 + a_c8);                                \
        CP16(s32(stg) + ST_BH + (a_row * SPAD + a_c8) * 2,                                 \
             Bhb + (size_t)a_row * DD + _k0 + a_c8);                                       \
        CP16(s32(stg) + ST_BL + (a_row * SPAD + a_c8) * 2,                                 \
             Blb + (size_t)a_row * DD + _k0 + a_c8);                                       \
        CP_COMMIT();                                                                       \
    } while (0)

    float acc[4][2][4] = {};

    PROJ_ISSUE(0, sm);
    PROJ_ISSUE(1, sm + STAGE_BYTES);
    PROJ_ISSUE(2, sm + 2 * STAGE_BYTES);

    const int NK = DD / 32;
    for (int k = 0; k < NK; k++) {
        char* cur = sm + (k % 3) * STAGE_BYTES;
        CP_WAIT2();
        __syncthreads();
        block_mma<4, 2, SPAD, 32>((u16*)(cur + ST_AH), (u16*)(cur + ST_AL),
                                  (u16*)(cur + ST_BH), (u16*)(cur + ST_BL),
                                  warp_m * 64, warp_n * 16, lane, acc);
        __syncthreads();
        if (k + 3 < NK) { PROJ_ISSUE(k + 3, cur); } else { CP_COMMIT(); }
    }
    CP_WAIT0();

    float* stg = (float*)sm;
    const int b = m0 >> 11, l0 = m0 & (LL - 1);
    for (int g = 0; g < 2; g++) {
        if ((warp_n >> 1) == g)
            stage_group<4, 2>(stg, warp_m, (warp_n & 1) * 16, lane, acc);
        __syncthreads();
        const int n_base = n0 + g * 32;
        if (MODE == 1) {
            const int h = n_base >> 6, cc = n_base & 63;
            float* dst = out + ((size_t)(b * HH + h) * DKK + cc) * LL + l0;
            for (int u = tid; u < 1024; u += 256) {
                const int c = u >> 5, l4 = (u & 31) << 2;
                const float bv = bias[n_base + c];
                float4 v;
                v.x = stg[(size_t)(l4 + 0) * 33 + c] + bv;
                v.y = stg[(size_t)(l4 + 1) * 33 + c] + bv;
                v.z = stg[(size_t)(l4 + 2) * 33 + c] + bv;
                v.w = stg[(size_t)(l4 + 3) * 33 + c] + bv;
                *(float4*)(dst + (size_t)c * LL + l4) = v;
            }
        } else {
            for (int u = tid; u < 1024; u += 256) {
                const int r = u >> 3, c4 = (u & 7) << 2;
                float4 v;
                v.x = stg[(size_t)r * 33 + c4 + 0] + bias[n_base + c4 + 0];
                v.y = stg[(size_t)r * 33 + c4 + 1] + bias[n_base + c4 + 1];
                v.z = stg[(size_t)r * 33 + c4 + 2] + bias[n_base + c4 + 2];
                v.w = stg[(size_t)r * 33 + c4 + 3] + bias[n_base + c4 + 3];
                if (MODE == 0) {
                    const int h = n_base >> 6, cc = (n_base & 63) + c4;
                    *(float4*)(out + ((size_t)(b * HH + h) * LL + l0 + r) * DKK + cc) = v;
                } else {
                    *(float4*)(out + (size_t)(m0 + r) * DD + n_base + c4) = v;
                }
            }
        }
        __syncthreads();
    }
    #undef PROJ_ISSUE
}

__global__ void __launch_bounds__(256, 2)
scores_mma(const float* __restrict__ q, const float* __restrict__ k,
           float* __restrict__ attn) {
    const int qt = (gridDim.x - 1) - blockIdx.x;
    const int bhid = blockIdx.y;
    const int q0 = qt * 128;
    extern __shared__ char sm[];
    const int tid = threadIdx.x, lane = tid & 31, wid = tid >> 5;
    const int warp_m = wid & 1, warp_n = wid >> 1;

    float* attnb = attn + ((size_t)bhid * LL + q0) * LL;
    const float* ks = k + (size_t)bhid * LL * DKK;

    load_split64((u16*)(sm + SC_QH), (u16*)(sm + SC_QL),
                 q + ((size_t)bhid * LL + q0) * DKK, DKK, tid);
    float4 kbuf[8];
    ldg_k(kbuf, ks, tid);
    __syncthreads();

    const int rbase = warp_m * 64 + (lane >> 2);
    const int cbase = warp_n * 32 + (lane & 3) * 2;

    for (int kt = 0; kt <= qt; kt++) {
        sts_k(kbuf, sm + SC_KH, sm + SC_KL, tid);
        __syncthreads();

        float acc[4][4][4] = {};
        block_mma<4, 4, SPAD2, 64>((u16*)(sm + SC_QH), (u16*)(sm + SC_QL),
                                   (u16*)(sm + SC_KH), (u16*)(sm + SC_KL),
                                   warp_m * 64, warp_n * 32, lane, acc);

        if (kt < qt) ldg_k(kbuf, ks + (size_t)(kt + 1) * 128 * DKK, tid);

        #pragma unroll
        for (int i = 0; i < 4; i++)
            #pragma unroll
            for (int p = 0; p < 2; p++) {
                const int r = rbase + i * 16 + p * 8;
                float* rowp = attnb + (size_t)r * LL + kt * 128 + cbase;
                #pragma unroll
                for (int j = 0; j < 4; j++) {
                    float2 v = make_float2(acc[i][j][p * 2] * 0.125f,
                                           acc[i][j][p * 2 + 1] * 0.125f);
                    *(float2*)(rowp + j * 8) = v;
                }
            }
        __syncthreads();
    }

    for (int kt = qt + 1; kt < LL / 128; kt++) {
        const float4 z = make_float4(0.f, 0.f, 0.f, 0.f);
        for (int u = tid; u < 128 * 32; u += 256) {
            const int r = u >> 5, c4 = (u & 31) << 2;
            *(float4*)(attnb + (size_t)r * LL + kt * 128 + c4) = z;
        }
    }
}

__global__ void softmax_kernel(float* __restrict__ attn) {
    const int row = blockIdx.x, bh = blockIdx.y;
    float* p = attn + ((size_t)bh * LL + row) * LL;
    const int valid = row + 1;
    const int nend = (((row >> 7) + 1) << 7);
    const int tid = threadIdx.x;

    __shared__ float sred[8];

    float4 v[2];
    float m = -3.4e38f;
    #pragma unroll
    for (int i = 0; i < 2; i++) {
        const int j = (tid + i * 256) * 4;
        if (j < nend) {
            v[i] = *(const float4*)(p + j);
            if (j + 0 < valid) m = fmaxf(m, v[i].x);
            if (j + 1 < valid) m = fmaxf(m, v[i].y);
            if (j + 2 < valid) m = fmaxf(m, v[i].z);
            if (j + 3 < valid) m = fmaxf(m, v[i].w);
        }
    }
    #pragma unroll
    for (int o = 16; o > 0; o >>= 1) m = fmaxf(m, __shfl_xor_sync(0xffffffff, m, o));
    if ((tid & 31) == 0) sred[tid >> 5] = m;
    __syncthreads();
    m = sred[0];
    #pragma unroll
    for (int w = 1; w < 8; w++) m = fmaxf(m, sred[w]);

    float sum = 0.0f;
    #pragma unroll
    for (int i = 0; i < 2; i++) {
        const int j = (tid + i * 256) * 4;
        if (j < nend) {
            v[i].x = (j + 0 < valid) ? __expf(v[i].x - m) : 0.0f;
            v[i].y = (j + 1 < valid) ? __expf(v[i].y - m) : 0.0f;
            v[i].z = (j + 2 < valid) ? __expf(v[i].z - m) : 0.0f;
            v[i].w = (j + 3 < valid) ? __expf(v[i].w - m) : 0.0f;
            sum += v[i].x + v[i].y + v[i].z + v[i].w;
        }
    }
    __syncthreads();
    #pragma unroll
    for (int o = 16; o > 0; o >>= 1) sum += __shfl_xor_sync(0xffffffff, sum, o);
    if ((tid & 31) == 0) sred[tid >> 5] = sum;
    __syncthreads();
    sum = 0.0f;
    #pragma unroll
    for (int w = 0; w < 8; w++) sum += sred[w];
    const float inv = 1.0f / sum;

    #pragma unroll
    for (int i = 0; i < 2; i++) {
        const int j = (tid + i * 256) * 4;
        if (j < nend) {
            float4 o4;
            o4.x = v[i].x * inv; o4.y = v[i].y * inv;
            o4.z = v[i].z * inv; o4.w = v[i].w * inv;
            *(float4*)(p + j) = o4;
        }
    }
}

__global__ void __launch_bounds__(256, 2)
av_mma(const float* __restrict__ attn, const float* __restrict__ vt,
       float* __restrict__ oc) {
    const int qt = (gridDim.x - 1) - blockIdx.x;
    const int bhid = blockIdx.y;
    const int b = bhid >> 4, h = bhid & 15;
    extern __shared__ char sm[];
    const int tid = threadIdx.x, lane = tid & 31, wid = tid >> 5;
    const int warp_m = wid & 1, warp_n = wid >> 1;
    const int q0 = qt * 128;

    const float* Pb = attn + ((size_t)bhid * LL + q0) * LL;
    const float* Vb = vt + (size_t)bhid * DKK * LL;

    float acc[4][2][4] = {};
    float4 ra[4], rb[2];

    const int NK = (qt + 1) * 4;

    ldg_chunk<4>(ra, Pb, LL, tid);
    ldg_chunk<2>(rb, Vb, LL, tid);
    {
        char* s0 = sm;
        sts_chunk<4>(ra, (u16*)(s0 + ST_AH), (u16*)(s0 + ST_AL), tid);
        sts_chunk<2>(rb, (u16*)(s0 + ST_BH), (u16*)(s0 + ST_BL), tid);
    }
    ldg_chunk<4>(ra, Pb + 32, LL, tid);
    ldg_chunk<2>(rb, Vb + 32, LL, tid);
    __syncthreads();

    for (int k = 0; k < NK; k++) {
        char* cur = sm + (k & 1) * STAGE_BYTES;
        block_mma<4, 2, SPAD, 32>((u16*)(cur + ST_AH), (u16*)(cur + ST_AL),
                                  (u16*)(cur + ST_BH), (u16*)(cur + ST_BL),
                                  warp_m * 64, warp_n * 16, lane, acc);
        if (k + 1 < NK) {
            char* nxt = sm + ((k + 1) & 1) * STAGE_BYTES;
            sts_chunk<4>(ra, (u16*)(nxt + ST_AH), (u16*)(nxt + ST_AL), tid);
            sts_chunk<2>(rb, (u16*)(nxt + ST_BH), (u16*)(nxt + ST_BL), tid);
        }
        if (k + 2 < NK) {
            ldg_chunk<4>(ra, Pb + (k + 2) * 32, LL, tid);
            ldg_chunk<2>(rb, Vb + (k + 2) * 32, LL, tid);
        }
        __syncthreads();
    }

    const int rbase = warp_m * 64 + (lane >> 2);
    const int cbase = warp_n * 16 + (lane & 3) * 2;
    #pragma unroll
    for (int i = 0; i < 4; i++)
        #pragma unroll
        for (int p = 0; p < 2; p++) {
            const int r = rbase + i * 16 + p * 8;
            float* rowp = oc + (size_t)(b * LL + q0 + r) * DD + h * DKK + cbase;
            #pragma unroll
            for (int j = 0; j < 2; j++) {
                float2 v = make_float2(acc[i][j][p * 2], acc[i][j][p * 2 + 1]);
                *(float2*)(rowp + j * 8) = v;
            }
        }
}

extern "C" void kernel_launch(void* const* d_in, const int* in_sizes, int n_in,
                              void* d_out, int out_size) {
    const float* x  = (const float*)d_in[0];
    const float* Wq = (const float*)d_in[2];
    const float* bq = (const float*)d_in[3];
    const float* Wk = (const float*)d_in[4];
    const float* bk = (const float*)d_in[5];
    const float* Wv = (const float*)d_in[6];
    const float* bv = (const float*)d_in[7];
    const float* Wo = (const float*)d_in[8];
    const float* bo = (const float*)d_in[9];
    float* out = (float*)d_out;

    const size_t out_elems  = (size_t)BB * LL * DD;
    const size_t attn_elems = (size_t)BH * LL * LL;

    u16 *xh, *xl, *wh, *wl, *och, *ocl;
    float *q, *k, *vt, *oc, *attn;
    cudaGetSymbolAddress((void**)&xh, g_xh); cudaGetSymbolAddress((void**)&xl, g_xl);
    cudaGetSymbolAddress((void**)&wh, g_wh); cudaGetSymbolAddress((void**)&wl, g_wl);
    cudaGetSymbolAddress((void**)&och, g_och); cudaGetSymbolAddress((void**)&ocl, g_ocl);
    cudaGetSymbolAddress((void**)&q,  g_q);
    cudaGetSymbolAddress((void**)&k,  g_k);
    cudaGetSymbolAddress((void**)&vt, g_vt);
    cudaGetSymbolAddress((void**)&oc, g_oc);
    if ((size_t)out_size >= out_elems + attn_elems) {
        attn = out + out_elems;
    } else {
        cudaGetSymbolAddress((void**)&attn, g_attn_scratch);
    }

    cudaFuncSetAttribute(gemm_proj<0>, cudaFuncAttributeMaxDynamicSharedMemorySize, PROJ_SMEM);
    cudaFuncSetAttribute(gemm_proj<1>, cudaFuncAttributeMaxDynamicSharedMemorySize, PROJ_SMEM);
    cudaFuncSetAttribute(gemm_proj<2>, cudaFuncAttributeMaxDynamicSharedMemorySize, PROJ_SMEM);
    cudaFuncSetAttribute(scores_mma,   cudaFuncAttributeMaxDynamicSharedMemorySize, SC_SMEM);
    cudaFuncSetAttribute(av_mma,       cudaFuncAttributeMaxDynamicSharedMemorySize, PIPE_SMEM);

    split_all<<<(XU + 4 * WU) / 256, 256>>>(x, Wq, Wk, Wv, Wo, xh, xl, wh, wl);

    dim3 projGrid(DD / 64, MROWS / 128);
    gemm_proj<0><<<projGrid, 256, PROJ_SMEM>>>(xh, xl, wh + (size_t)0 * DD * DD, wl + (size_t)0 * DD * DD, bq, q);
    gemm_proj<0><<<projGrid, 256, PROJ_SMEM>>>(xh, xl, wh + (size_t)1 * DD * DD, wl + (size_t)1 * DD * DD, bk, k);
    gemm_proj<1><<<projGrid, 256, PROJ_SMEM>>>(xh, xl, wh + (size_t)2 * DD * DD, wl + (size_t)2 * DD * DD, bv, vt);

    dim3 scoreGrid(LL / 128, BH);
    scores_mma<<<scoreGrid, 256, SC_SMEM>>>(q, k, attn);

    dim3 smGrid(LL, BH);
    softmax_kernel<<<smGrid, 256>>>(attn);

    dim3 avGrid(LL / 128, BH);
    av_mma<<<avGrid, 256, PIPE_SMEM>>>(attn, vt, oc);

    split_oc<<<(MROWS * DD / 4) / 256, 256>>>(oc, och, ocl);
    gemm_proj<2><<<projGrid, 256, PROJ_SMEM>>>(och, ocl, wh + (size_t)3 * DD * DD, wl + (size_t)3 * DD * DD, bo, out);
}

// round 13
// speedup vs baseline: 1.0057x; 1.0057x over previous
#include <cuda_runtime.h>
#include <cuda_bf16.h>
#include <cstdint>
#include <math.h>

#define BB 4
#define LL 2048
#define DD 1024
#define HH 16
#define DKK 64
#define BH (BB*HH)        // 64
#define MROWS (BB*LL)     // 8192

#define SPAD 40           // smem row stride (bf16) for K=32 chunks
#define SPAD2 72          // smem row stride (bf16) for K=64 tiles (scores)

// pipelined-stage smem layout (proj / wav): per stage
#define ST_AH 0
#define ST_AL 10240       // 128*40*2
#define ST_BH 20480
#define ST_BL 25600       // 64*40*2
#define STAGE_BYTES 30720
#define PIPE_SMEM (2*STAGE_BYTES)      // 61440
#define WSTAT (2*STAGE_BYTES)          // float2[128] stats region (wav)
#define WAV_SMEM (2*STAGE_BYTES + 1024)

// scores smem layout
#define SC_QH 0
#define SC_QL 18432       // 128*72*2
#define SC_KH 36864
#define SC_KL 55296
#define SC_RED 73728      // float2[128][4] = 4096
#define SC_SMEM 77824

// ---------------- device scratch (allocation-free) ----------------
__device__ float g_q[(size_t)BH * LL * DKK];     // [bh][l][dk]
__device__ float g_k[(size_t)BH * LL * DKK];
__device__ float g_vt[(size_t)BH * DKK * LL];    // [bh][dk][l]  (V transposed)
__device__ float g_oc[(size_t)MROWS * DD];       // concat attention output
__device__ float2 g_part[(size_t)BH * LL * 4];   // per (row, strip) softmax partials
__device__ float2 g_rowstats[(size_t)BH * LL];   // per row (max, 1/sum)
__device__ float g_attn_scratch[(size_t)BH * LL * LL]; // fallback

// ---------------- mma helpers ----------------
__device__ __forceinline__ uint32_t s32(const void* p) {
    return (uint32_t)__cvta_generic_to_shared(p);
}

#define LDSM_X4(R, a)                                                          \
    asm volatile("ldmatrix.sync.aligned.m8n8.x4.shared.b16 {%0,%1,%2,%3}, [%4];" \
        : "=r"((R)[0]), "=r"((R)[1]), "=r"((R)[2]), "=r"((R)[3]) : "r"(a))
#define LDSM_X2(R, a)                                                          \
    asm volatile("ldmatrix.sync.aligned.m8n8.x2.shared.b16 {%0,%1}, [%2];"     \
        : "=r"((R)[0]), "=r"((R)[1]) : "r"(a))

__device__ __forceinline__ void mma_bf16(float* c, const uint32_t* a, const uint32_t* b) {
    asm volatile(
        "mma.sync.aligned.m16n8k16.row.col.f32.bf16.bf16.f32 "
        "{%0,%1,%2,%3}, {%4,%5,%6,%7}, {%8,%9}, {%0,%1,%2,%3};"
        : "+f"(c[0]), "+f"(c[1]), "+f"(c[2]), "+f"(c[3])
        : "r"(a[0]), "r"(a[1]), "r"(a[2]), "r"(a[3]), "r"(b[0]), "r"(b[1]));
}

__device__ __forceinline__ void cvt_split(const float4& v, uint2& hv, uint2& lv) {
    __nv_bfloat16 h0 = __float2bfloat16(v.x), h1 = __float2bfloat16(v.y);
    __nv_bfloat16 h2 = __float2bfloat16(v.z), h3 = __float2bfloat16(v.w);
    __nv_bfloat16 l0 = __float2bfloat16(v.x - __bfloat162float(h0));
    __nv_bfloat16 l1 = __float2bfloat16(v.y - __bfloat162float(h1));
    __nv_bfloat16 l2 = __float2bfloat16(v.z - __bfloat162float(h2));
    __nv_bfloat16 l3 = __float2bfloat16(v.w - __bfloat162float(h3));
    hv.x = ((uint32_t)__bfloat16_as_ushort(h1) << 16) | __bfloat16_as_ushort(h0);
    hv.y = ((uint32_t)__bfloat16_as_ushort(h3) << 16) | __bfloat16_as_ushort(h2);
    lv.x = ((uint32_t)__bfloat16_as_ushort(l1) << 16) | __bfloat16_as_ushort(l0);
    lv.y = ((uint32_t)__bfloat16_as_ushort(l3) << 16) | __bfloat16_as_ushort(l2);
}

// ---- pipelined chunk helpers: [rows x 32] fp32 (row stride ld) ----
template <int N4>
__device__ __forceinline__ void ldg_chunk(float4 (&r)[N4], const float* __restrict__ g,
                                          int ld, int tid) {
    #pragma unroll
    for (int i = 0; i < N4; i++) {
        const int u = tid + i * 256;
        const int row = u >> 3, c4 = (u & 7) << 2;
        r[i] = *(const float4*)(g + (size_t)row * ld + c4);
    }
}
template <int N4>
__device__ __forceinline__ void sts_chunk(const float4 (&v)[N4], __nv_bfloat16* shi,
                                          __nv_bfloat16* slo, int tid) {
    #pragma unroll
    for (int i = 0; i < N4; i++) {
        const int u = tid + i * 256;
        const int row = u >> 3, c4 = (u & 7) << 2;
        uint2 hv, lv; cvt_split(v[i], hv, lv);
        *(uint2*)(shi + row * SPAD + c4) = hv;
        *(uint2*)(slo + row * SPAD + c4) = lv;
    }
}

// wav staging: raw S chunk -> normalized W (masked), STG back + split to smem
__device__ __forceinline__ void sts_w(const float4 (&v)[4], __nv_bfloat16* shi,
                                      __nv_bfloat16* slo, float* attnb,
                                      const float2* sstat, int q0, int c0, int tid) {
    #pragma unroll
    for (int i = 0; i < 4; i++) {
        const int u = tid + i * 256;
        const int row = u >> 3, c4 = (u & 7) << 2;
        const float2 st = sstat[row];
        const int grow = q0 + row, cg = c0 + c4;
        float4 w;
        w.x = (cg + 0 <= grow) ? __expf(v[i].x - st.x) * st.y : 0.f;
        w.y = (cg + 1 <= grow) ? __expf(v[i].y - st.x) * st.y : 0.f;
        w.z = (cg + 2 <= grow) ? __expf(v[i].z - st.x) * st.y : 0.f;
        w.w = (cg + 3 <= grow) ? __expf(v[i].w - st.x) * st.y : 0.f;
        *(float4*)(attnb + (size_t)row * LL + c0 + c4) = w;
        uint2 hv, lv; cvt_split(w, hv, lv);
        *(uint2*)(shi + row * SPAD + c4) = hv;
        *(uint2*)(slo + row * SPAD + c4) = lv;
    }
}

// [128 x 64] fp32 (row stride ld) -> split hi/lo bf16 smem (stride SPAD2)
__device__ __forceinline__ void load_split64(__nv_bfloat16* shi, __nv_bfloat16* slo,
                                             const float* __restrict__ g, int ld, int tid) {
    #pragma unroll
    for (int i = 0; i < 8; i++) {
        const int u = tid + i * 256;
        const int r = u >> 4, c4 = (u & 15) << 2;
        float4 v = *(const float4*)(g + (size_t)r * ld + c4);
        uint2 hv, lv; cvt_split(v, hv, lv);
        *(uint2*)(shi + r * SPAD2 + c4) = hv;
        *(uint2*)(slo + r * SPAD2 + c4) = lv;
    }
}

// K tile [128x64] register prefetch + split store (stride SPAD2)
__device__ __forceinline__ void ldg_k(float4 (&r)[8], const float* __restrict__ g, int tid) {
    #pragma unroll
    for (int i = 0; i < 8; i++) {
        const int u = tid + i * 256;
        r[i] = *(const float4*)(g + (size_t)(u >> 4) * DKK + ((u & 15) << 2));
    }
}
__device__ __forceinline__ void sts_k(const float4 (&v)[8], char* hi, char* lo, int tid) {
    #pragma unroll
    for (int i = 0; i < 8; i++) {
        const int u = tid + i * 256;
        const int r = u >> 4, c4 = (u & 15) << 2;
        uint2 hv, lv; cvt_split(v[i], hv, lv);
        *(uint2*)((__nv_bfloat16*)hi + r * SPAD2 + c4) = hv;
        *(uint2*)((__nv_bfloat16*)lo + r * SPAD2 + c4) = lv;
    }
}

// One K-chunk of split-bf16 3-pass MMA (AhBh + AhBl + AlBh).
template <int MT, int NT, int STRIDE, int KC>
__device__ __forceinline__ void block_mma(
    const __nv_bfloat16* sAh, const __nv_bfloat16* sAl,
    const __nv_bfloat16* sBh, const __nv_bfloat16* sBl,
    int a_row0, int b_row0, int lane, float (&acc)[MT][NT][4]) {
    #pragma unroll
    for (int kb = 0; kb < KC; kb += 16) {
        uint32_t ah[MT][4], al[MT][4], bh[NT][2], bl[NT][2];
        const int ar = a_row0 + (lane & 15);
        const int ac = kb + ((lane >> 4) << 3);
        #pragma unroll
        for (int i = 0; i < MT; i++) {
            LDSM_X4(ah[i], s32(sAh + (ar + i * 16) * STRIDE + ac));
            LDSM_X4(al[i], s32(sAl + (ar + i * 16) * STRIDE + ac));
        }
        const int br = b_row0 + (lane & 7);
        const int bc = kb + (((lane >> 3) & 1) << 3);
        #pragma unroll
        for (int j = 0; j < NT; j++) {
            LDSM_X2(bh[j], s32(sBh + (br + j * 8) * STRIDE + bc));
            LDSM_X2(bl[j], s32(sBl + (br + j * 8) * STRIDE + bc));
        }
        #pragma unroll
        for (int i = 0; i < MT; i++)
            #pragma unroll
            for (int j = 0; j < NT; j++) {
                mma_bf16(acc[i][j], ah[i], bh[j]);
                mma_bf16(acc[i][j], ah[i], bl[j]);
                mma_bf16(acc[i][j], al[i], bh[j]);
            }
    }
}

// Stage a 32-col accumulator group into fp32 smem [128][33] (proj epilogue).
template <int MT, int NT>
__device__ __forceinline__ void stage_group(float* stg, int warp_m, int col_base, int lane,
                                            float (&acc)[MT][NT][4], float scale) {
    const int r0 = warp_m * MT * 16 + (lane >> 2);
    const int c0 = (lane & 3) * 2;
    #pragma unroll
    for (int i = 0; i < MT; i++)
        #pragma unroll
        for (int j = 0; j < NT; j++) {
            float* p = stg + (size_t)(r0 + i * 16) * 33 + col_base + j * 8 + c0;
            p[0] = acc[i][j][0] * scale;
            p[1] = acc[i][j][1] * scale;
            p[8 * 33 + 0] = acc[i][j][2] * scale;
            p[8 * 33 + 1] = acc[i][j][3] * scale;
        }
}

// ================= projection GEMM: C = A @ W^T + bias (tile 128x64, pipelined) ====
template <int MODE>
__global__ void __launch_bounds__(256, 2)
gemm_proj(const float* __restrict__ A, const float* __restrict__ W,
          const float* __restrict__ bias, float* __restrict__ out) {
    extern __shared__ char sm[];
    const int tid = threadIdx.x, lane = tid & 31, wid = tid >> 5;
    const int warp_m = wid & 1, warp_n = wid >> 1;     // 2 x 4; warp tile 64x16
    const int m0 = blockIdx.y * 128, n0 = blockIdx.x * 64;

    const float* Ab = A + (size_t)m0 * DD;
    const float* Wb = W + (size_t)n0 * DD;

    float acc[4][2][4] = {};
    float4 ra[4], rb[2];

    ldg_chunk<4>(ra, Ab, DD, tid);
    ldg_chunk<2>(rb, Wb, DD, tid);
    {
        char* s0 = sm;
        sts_chunk<4>(ra, (__nv_bfloat16*)(s0 + ST_AH), (__nv_bfloat16*)(s0 + ST_AL), tid);
        sts_chunk<2>(rb, (__nv_bfloat16*)(s0 + ST_BH), (__nv_bfloat16*)(s0 + ST_BL), tid);
    }
    ldg_chunk<4>(ra, Ab + 32, DD, tid);
    ldg_chunk<2>(rb, Wb + 32, DD, tid);
    __syncthreads();

    const int NK = DD / 32;   // 32
    for (int k = 0; k < NK; k++) {
        char* cur = sm + (k & 1) * STAGE_BYTES;
        block_mma<4, 2, SPAD, 32>((__nv_bfloat16*)(cur + ST_AH), (__nv_bfloat16*)(cur + ST_AL),
                                  (__nv_bfloat16*)(cur + ST_BH), (__nv_bfloat16*)(cur + ST_BL),
                                  warp_m * 64, warp_n * 16, lane, acc);
        if (k + 1 < NK) {
            char* nxt = sm + ((k + 1) & 1) * STAGE_BYTES;
            sts_chunk<4>(ra, (__nv_bfloat16*)(nxt + ST_AH), (__nv_bfloat16*)(nxt + ST_AL), tid);
            sts_chunk<2>(rb, (__nv_bfloat16*)(nxt + ST_BH), (__nv_bfloat16*)(nxt + ST_BL), tid);
        }
        if (k + 2 < NK) {
            ldg_chunk<4>(ra, Ab + (k + 2) * 32, DD, tid);
            ldg_chunk<2>(rb, Wb + (k + 2) * 32, DD, tid);
        }
        __syncthreads();
    }

    float* stg = (float*)sm;
    const int b = m0 >> 11, l0 = m0 & (LL - 1);
    for (int g = 0; g < 2; g++) {
        if ((warp_n >> 1) == g)
            stage_group<4, 2>(stg, warp_m, (warp_n & 1) * 16, lane, acc, 1.0f);
        __syncthreads();
        const int n_base = n0 + g * 32;
        if (MODE == 1) {
            const int h = n_base >> 6, cc = n_base & 63;
            float* dst = out + ((size_t)(b * HH + h) * DKK + cc) * LL + l0;
            for (int u = tid; u < 1024; u += 256) {
                const int c = u >> 5, l4 = (u & 31) << 2;
                const float bv = bias[n_base + c];
                float4 v;
                v.x = stg[(size_t)(l4 + 0) * 33 + c] + bv;
                v.y = stg[(size_t)(l4 + 1) * 33 + c] + bv;
                v.z = stg[(size_t)(l4 + 2) * 33 + c] + bv;
                v.w = stg[(size_t)(l4 + 3) * 33 + c] + bv;
                *(float4*)(dst + (size_t)c * LL + l4) = v;
            }
        } else {
            for (int u = tid; u < 1024; u += 256) {
                const int r = u >> 3, c4 = (u & 7) << 2;
                float4 v;
                v.x = stg[(size_t)r * 33 + c4 + 0] + bias[n_base + c4 + 0];
                v.y = stg[(size_t)r * 33 + c4 + 1] + bias[n_base + c4 + 1];
                v.z = stg[(size_t)r * 33 + c4 + 2] + bias[n_base + c4 + 2];
                v.w = stg[(size_t)r * 33 + c4 + 3] + bias[n_base + c4 + 3];
                if (MODE == 0) {
                    const int h = n_base >> 6, cc = (n_base & 63) + c4;
                    *(float4*)(out + ((size_t)(b * HH + h) * LL + l0 + r) * DKK + cc) = v;
                } else {
                    *(float4*)(out + (size_t)(m0 + r) * DD + n_base + c4) = v;
                }
            }
        }
        __syncthreads();
    }
}

// ===== scores: strips of 4 kt-tiles; direct STG epilogue + online (m,l) partials ====
__global__ void __launch_bounds__(256, 2)
scores_mma(const float* __restrict__ q, const float* __restrict__ k,
           float* __restrict__ attn, float2* __restrict__ part) {
    const int strip = blockIdx.x, qt = blockIdx.y, bhid = blockIdx.z;
    const int kt0 = strip * 4;
    const int q0 = qt * 128;
    extern __shared__ char sm[];
    const int tid = threadIdx.x, lane = tid & 31, wid = tid >> 5;
    const int warp_m = wid & 1, warp_n = wid >> 1;     // 2 x 4; warp tile 64x32

    float* attnb = attn + ((size_t)bhid * LL + q0) * LL;

    if (kt0 > qt) {
        const float4 z = make_float4(0.f, 0.f, 0.f, 0.f);
        for (int u = tid; u < 128 * 128; u += 256) {
            const int r = u >> 7, c4 = (u & 127) << 2;
            *(float4*)(attnb + (size_t)r * LL + kt0 * 128 + c4) = z;
        }
        return;
    }

    load_split64((__nv_bfloat16*)(sm + SC_QH), (__nv_bfloat16*)(sm + SC_QL),
                 q + ((size_t)bhid * LL + q0) * DKK, DKK, tid);
    float4 kbuf[8];
    ldg_k(kbuf, k + ((size_t)bhid * LL + kt0 * 128) * DKK, tid);
    __syncthreads();

    const int rbase = warp_m * 64 + (lane >> 2);
    const int cbase = warp_n * 32 + (lane & 3) * 2;

    float run_m[4][2], run_l[4][2];
    #pragma unroll
    for (int i = 0; i < 4; i++) {
        run_m[i][0] = run_m[i][1] = -1e30f;
        run_l[i][0] = run_l[i][1] = 0.f;
    }

    for (int kt = kt0; kt < kt0 + 4; kt++) {
        if (kt <= qt) {
            sts_k(kbuf, sm + SC_KH, sm + SC_KL, tid);
            __syncthreads();

            float acc[4][4][4] = {};
            block_mma<4, 4, SPAD2, 64>((__nv_bfloat16*)(sm + SC_QH), (__nv_bfloat16*)(sm + SC_QL),
                                       (__nv_bfloat16*)(sm + SC_KH), (__nv_bfloat16*)(sm + SC_KL),
                                       warp_m * 64, warp_n * 32, lane, acc);

            if (kt + 1 <= qt && kt + 1 < kt0 + 4)
                ldg_k(kbuf, k + ((size_t)bhid * LL + (kt + 1) * 128) * DKK, tid);

            // direct STG.64 epilogue + online (m,l) update
            const bool diag = (kt == qt);
            #pragma unroll
            for (int i = 0; i < 4; i++)
                #pragma unroll
                for (int p = 0; p < 2; p++) {
                    const int r = rbase + i * 16 + p * 8;
                    float* rowp = attnb + (size_t)r * LL + kt * 128 + cbase;
                    float sv[8];
                    float tmax = -1e30f;
                    #pragma unroll
                    for (int j = 0; j < 4; j++) {
                        const float s0 = acc[i][j][p * 2] * 0.125f;
                        const float s1 = acc[i][j][p * 2 + 1] * 0.125f;
                        *(float2*)(rowp + j * 8) = make_float2(s0, s1);
                        sv[j * 2 + 0] = (!diag || (cbase + j * 8 + 0 <= r)) ? s0 : -1e30f;
                        sv[j * 2 + 1] = (!diag || (cbase + j * 8 + 1 <= r)) ? s1 : -1e30f;
                        tmax = fmaxf(tmax, fmaxf(sv[j * 2], sv[j * 2 + 1]));
                    }
                    float l8 = 0.f;
                    #pragma unroll
                    for (int e = 0; e < 8; e++) l8 += __expf(sv[e] - tmax);
                    const float mn = fmaxf(run_m[i][p], tmax);
                    run_l[i][p] = run_l[i][p] * __expf(run_m[i][p] - mn)
                                + l8 * __expf(tmax - mn);
                    run_m[i][p] = mn;
                }
            __syncthreads();   // K buffer reuse guard
        } else {
            const float4 z = make_float4(0.f, 0.f, 0.f, 0.f);
            for (int u = tid; u < 128 * 32; u += 256) {
                const int r = u >> 5, c4 = (u & 31) << 2;
                *(float4*)(attnb + (size_t)r * LL + kt * 128 + c4) = z;
            }
        }
    }

    // cross-thread reduce of strip (m,l): 4 lanes x 4 warp_n cover each row
    float2* red = (float2*)(sm + SC_RED);
    #pragma unroll
    for (int i = 0; i < 4; i++)
        #pragma unroll
        for (int p = 0; p < 2; p++) {
            float m = run_m[i][p], l = run_l[i][p];
            #pragma unroll
            for (int off = 1; off <= 2; off <<= 1) {
                float m2 = __shfl_xor_sync(0xffffffffu, m, off);
                float l2 = __shfl_xor_sync(0xffffffffu, l, off);
                float mn = fmaxf(m, m2);
                l = l * __expf(m - mn) + l2 * __expf(m2 - mn);
                m = mn;
            }
            if ((lane & 3) == 0)
                red[(rbase + i * 16 + p * 8) * 4 + warp_n] = make_float2(m, l);
        }
    __syncthreads();
    if (tid < 128) {
        float m = -1e30f, l = 0.f;
        #pragma unroll
        for (int w = 0; w < 4; w++) {
            float2 v = red[tid * 4 + w];
            float mn = fmaxf(m, v.x);
            l = l * __expf(m - mn) + v.y * __expf(v.x - mn);
            m = mn;
        }
        part[((size_t)bhid * LL + q0 + tid) * 4 + strip] = make_float2(m, l);
    }
}

// ================= stats reduce: fold <=4 strip partials per row =================
__global__ void stats_reduce(const float2* __restrict__ part,
                             float2* __restrict__ rowstats) {
    const int idx = blockIdx.x * 256 + threadIdx.x;   // BH*LL = 131072
    const int row = idx & (LL - 1);
    const int nstrips = ((row >> 7) >> 2) + 1;        // 1..4
    const float2* p = part + (size_t)idx * 4;
    float m = -1e30f, l = 0.f;
    for (int t = 0; t < nstrips; t++) {
        float2 v = p[t];
        float mn = fmaxf(m, v.x);
        l = l * __expf(m - mn) + v.y * __expf(v.x - mn);
        m = mn;
    }
    rowstats[idx] = make_float2(m, 1.0f / l);
}

// ====== wav: normalize raw S -> W (write once) + O = W.V, av-style pipeline ======
__global__ void __launch_bounds__(256, 2)
wav_mma(float* __restrict__ attn, const float* __restrict__ vt,
        const float2* __restrict__ rowstats, float* __restrict__ oc) {
    const int qt = (gridDim.x - 1) - blockIdx.x;   // heavy blocks first
    const int bhid = blockIdx.y;
    const int b = bhid >> 4, h = bhid & 15;
    extern __shared__ char sm[];
    const int tid = threadIdx.x, lane = tid & 31, wid = tid >> 5;
    const int warp_m = wid & 1, warp_n = wid >> 1;
    const int q0 = qt * 128;

    float* attnb = attn + ((size_t)bhid * LL + q0) * LL;
    const float* Vb = vt + (size_t)bhid * DKK * LL;
    float2* sstat = (float2*)(sm + WSTAT);

    if (tid < 128) sstat[tid] = rowstats[(size_t)bhid * LL + q0 + tid];
    __syncthreads();

    float acc[4][2][4] = {};
    float4 ra[4], rb[2];

    const int NK = (qt + 1) * 4;

    ldg_chunk<4>(ra, attnb, LL, tid);
    ldg_chunk<2>(rb, Vb, LL, tid);
    {
        char* s0 = sm;
        sts_w(ra, (__nv_bfloat16*)(s0 + ST_AH), (__nv_bfloat16*)(s0 + ST_AL),
              attnb, sstat, q0, 0, tid);
        sts_chunk<2>(rb, (__nv_bfloat16*)(s0 + ST_BH), (__nv_bfloat16*)(s0 + ST_BL), tid);
    }
    ldg_chunk<4>(ra, attnb + 32, LL, tid);
    ldg_chunk<2>(rb, Vb + 32, LL, tid);
    __syncthreads();

    for (int k = 0; k < NK; k++) {
        char* cur = sm + (k & 1) * STAGE_BYTES;
        block_mma<4, 2, SPAD, 32>((__nv_bfloat16*)(cur + ST_AH), (__nv_bfloat16*)(cur + ST_AL),
                                  (__nv_bfloat16*)(cur + ST_BH), (__nv_bfloat16*)(cur + ST_BL),
                                  warp_m * 64, warp_n * 16, lane, acc);
        if (k + 1 < NK) {
            char* nxt = sm + ((k + 1) & 1) * STAGE_BYTES;
            sts_w(ra, (__nv_bfloat16*)(nxt + ST_AH), (__nv_bfloat16*)(nxt + ST_AL),
                  attnb, sstat, q0, (k + 1) * 32, tid);
            sts_chunk<2>(rb, (__nv_bfloat16*)(nxt + ST_BH), (__nv_bfloat16*)(nxt + ST_BL), tid);
        }
        if (k + 2 < NK) {
            ldg_chunk<4>(ra, attnb + (k + 2) * 32, LL, tid);
            ldg_chunk<2>(rb, Vb + (k + 2) * 32, LL, tid);
        }
        __syncthreads();
    }

    // direct STG.64 epilogue to concat layout
    const int rbase = warp_m * 64 + (lane >> 2);
    const int cbase = warp_n * 16 + (lane & 3) * 2;
    #pragma unroll
    for (int i = 0; i < 4; i++)
        #pragma unroll
        for (int p = 0; p < 2; p++) {
            const int r = rbase + i * 16 + p * 8;
            float* rowp = oc + (size_t)(b * LL + q0 + r) * DD + h * DKK + cbase;
            #pragma unroll
            for (int j = 0; j < 2; j++) {
                float2 v = make_float2(acc[i][j][p * 2], acc[i][j][p * 2 + 1]);
                *(float2*)(rowp + j * 8) = v;
            }
        }
}

// ---------------- launch ----------------
extern "C" void kernel_launch(void* const* d_in, const int* in_sizes, int n_in,
                              void* d_out, int out_size) {
    const float* x  = (const float*)d_in[0];
    const float* Wq = (const float*)d_in[2];
    const float* bq = (const float*)d_in[3];
    const float* Wk = (const float*)d_in[4];
    const float* bk = (const float*)d_in[5];
    const float* Wv = (const float*)d_in[6];
    const float* bv = (const float*)d_in[7];
    const float* Wo = (const float*)d_in[8];
    const float* bo = (const float*)d_in[9];
    float* out = (float*)d_out;

    const size_t out_elems  = (size_t)BB * LL * DD;
    const size_t attn_elems = (size_t)BH * LL * LL;

    float *q, *k, *vt, *oc, *attn;
    float2 *part, *rowstats;
    cudaGetSymbolAddress((void**)&q,  g_q);
    cudaGetSymbolAddress((void**)&k,  g_k);
    cudaGetSymbolAddress((void**)&vt, g_vt);
    cudaGetSymbolAddress((void**)&oc, g_oc);
    cudaGetSymbolAddress((void**)&part, g_part);
    cudaGetSymbolAddress((void**)&rowstats, g_rowstats);
    if ((size_t)out_size >= out_elems + attn_elems) {
        attn = out + out_elems;
    } else {
        cudaGetSymbolAddress((void**)&attn, g_attn_scratch);
    }

    cudaFuncSetAttribute(gemm_proj<0>, cudaFuncAttributeMaxDynamicSharedMemorySize, PIPE_SMEM);
    cudaFuncSetAttribute(gemm_proj<1>, cudaFuncAttributeMaxDynamicSharedMemorySize, PIPE_SMEM);
    cudaFuncSetAttribute(gemm_proj<2>, cudaFuncAttributeMaxDynamicSharedMemorySize, PIPE_SMEM);
    cudaFuncSetAttribute(scores_mma,   cudaFuncAttributeMaxDynamicSharedMemorySize, SC_SMEM);
    cudaFuncSetAttribute(wav_mma,      cudaFuncAttributeMaxDynamicSharedMemorySize, WAV_SMEM);

    dim3 projGrid(DD / 64, MROWS / 128);       // (16, 64)
    gemm_proj<0><<<projGrid, 256, PIPE_SMEM>>>(x, Wq, bq, q);
    gemm_proj<0><<<projGrid, 256, PIPE_SMEM>>>(x, Wk, bk, k);
    gemm_proj<1><<<projGrid, 256, PIPE_SMEM>>>(x, Wv, bv, vt);

    dim3 scoreGrid(4, LL / 128, BH);           // (4, 16, 64)
    scores_mma<<<scoreGrid, 256, SC_SMEM>>>(q, k, attn, part);

    stats_reduce<<<(BH * LL) / 256, 256>>>(part, rowstats);

    dim3 wavGrid(LL / 128, BH);                // (16, 64)
    wav_mma<<<wavGrid, 256, WAV_SMEM>>>(attn, vt, rowstats, oc);

    gemm_proj<2><<<projGrid, 256, PIPE_SMEM>>>(oc, Wo, bo, out);
}

// round 14
// speedup vs baseline: 1.0319x; 1.0260x over previous
#include <cuda_runtime.h>
#include <cuda_bf16.h>
#include <cstdint>
#include <math.h>

#define BB 4
#define LL 2048
#define DD 1024
#define HH 16
#define DKK 64
#define BH (BB*HH)        // 64
#define MROWS (BB*LL)     // 8192

#define SPAD 40           // smem row stride (bf16) for K=32 chunks
#define SPAD2 72          // smem row stride (bf16) for K=64 tiles (scores)

// pipelined-stage smem layout (proj / av): per stage
#define ST_AH 0
#define ST_AL 10240       // 128*40*2
#define ST_BH 20480
#define ST_BL 25600       // 64*40*2
#define STAGE_BYTES 30720
#define PIPE_SMEM (2*STAGE_BYTES)      // 61440

// scores smem layout
#define SC_QH 0
#define SC_QL 18432       // 128*72*2
#define SC_KH 36864
#define SC_KL 55296
#define SC_SMEM 73728

// ---------------- device scratch (allocation-free) ----------------
__device__ float g_q[(size_t)BH * LL * DKK];     // [bh][l][dk]
__device__ float g_k[(size_t)BH * LL * DKK];
__device__ float g_vt[(size_t)BH * DKK * LL];    // [bh][dk][l]  (V transposed)
__device__ float g_oc[(size_t)MROWS * DD];       // concat attention output
__device__ float g_attn_scratch[(size_t)BH * LL * LL]; // fallback

// ---------------- mma helpers ----------------
__device__ __forceinline__ uint32_t s32(const void* p) {
    return (uint32_t)__cvta_generic_to_shared(p);
}

#define LDSM_X4(R, a)                                                          \
    asm volatile("ldmatrix.sync.aligned.m8n8.x4.shared.b16 {%0,%1,%2,%3}, [%4];" \
        : "=r"((R)[0]), "=r"((R)[1]), "=r"((R)[2]), "=r"((R)[3]) : "r"(a))
#define LDSM_X2(R, a)                                                          \
    asm volatile("ldmatrix.sync.aligned.m8n8.x2.shared.b16 {%0,%1}, [%2];"     \
        : "=r"((R)[0]), "=r"((R)[1]) : "r"(a))

__device__ __forceinline__ void mma_bf16(float* c, const uint32_t* a, const uint32_t* b) {
    asm volatile(
        "mma.sync.aligned.m16n8k16.row.col.f32.bf16.bf16.f32 "
        "{%0,%1,%2,%3}, {%4,%5,%6,%7}, {%8,%9}, {%0,%1,%2,%3};"
        : "+f"(c[0]), "+f"(c[1]), "+f"(c[2]), "+f"(c[3])
        : "r"(a[0]), "r"(a[1]), "r"(a[2]), "r"(a[3]), "r"(b[0]), "r"(b[1]));
}

__device__ __forceinline__ void cvt_split(const float4& v, uint2& hv, uint2& lv) {
    __nv_bfloat16 h0 = __float2bfloat16(v.x), h1 = __float2bfloat16(v.y);
    __nv_bfloat16 h2 = __float2bfloat16(v.z), h3 = __float2bfloat16(v.w);
    __nv_bfloat16 l0 = __float2bfloat16(v.x - __bfloat162float(h0));
    __nv_bfloat16 l1 = __float2bfloat16(v.y - __bfloat162float(h1));
    __nv_bfloat16 l2 = __float2bfloat16(v.z - __bfloat162float(h2));
    __nv_bfloat16 l3 = __float2bfloat16(v.w - __bfloat162float(h3));
    hv.x = ((uint32_t)__bfloat16_as_ushort(h1) << 16) | __bfloat16_as_ushort(h0);
    hv.y = ((uint32_t)__bfloat16_as_ushort(h3) << 16) | __bfloat16_as_ushort(h2);
    lv.x = ((uint32_t)__bfloat16_as_ushort(l1) << 16) | __bfloat16_as_ushort(l0);
    lv.y = ((uint32_t)__bfloat16_as_ushort(l3) << 16) | __bfloat16_as_ushort(l2);
}

// ---- pipelined chunk helpers: [rows x 32] fp32 (row stride ld) ----
template <int N4>
__device__ __forceinline__ void ldg_chunk(float4 (&r)[N4], const float* __restrict__ g,
                                          int ld, int tid) {
    #pragma unroll
    for (int i = 0; i < N4; i++) {
        const int u = tid + i * 256;
        const int row = u >> 3, c4 = (u & 7) << 2;
        r[i] = *(const float4*)(g + (size_t)row * ld + c4);
    }
}
template <int N4>
__device__ __forceinline__ void sts_chunk(const float4 (&v)[N4], __nv_bfloat16* shi,
                                          __nv_bfloat16* slo, int tid) {
    #pragma unroll
    for (int i = 0; i < N4; i++) {
        const int u = tid + i * 256;
        const int row = u >> 3, c4 = (u & 7) << 2;
        uint2 hv, lv; cvt_split(v[i], hv, lv);
        *(uint2*)(shi + row * SPAD + c4) = hv;
        *(uint2*)(slo + row * SPAD + c4) = lv;
    }
}

// [128 x 64] fp32 (row stride ld) -> split hi/lo bf16 smem (stride SPAD2)
__device__ __forceinline__ void load_split64(__nv_bfloat16* shi, __nv_bfloat16* slo,
                                             const float* __restrict__ g, int ld, int tid) {
    #pragma unroll
    for (int i = 0; i < 8; i++) {
        const int u = tid + i * 256;
        const int r = u >> 4, c4 = (u & 15) << 2;
        float4 v = *(const float4*)(g + (size_t)r * ld + c4);
        uint2 hv, lv; cvt_split(v, hv, lv);
        *(uint2*)(shi + r * SPAD2 + c4) = hv;
        *(uint2*)(slo + r * SPAD2 + c4) = lv;
    }
}

// K tile [128x64] register prefetch + split store (stride SPAD2)
__device__ __forceinline__ void ldg_k(float4 (&r)[8], const float* __restrict__ g, int tid) {
    #pragma unroll
    for (int i = 0; i < 8; i++) {
        const int u = tid + i * 256;
        r[i] = *(const float4*)(g + (size_t)(u >> 4) * DKK + ((u & 15) << 2));
    }
}
__device__ __forceinline__ void sts_k(const float4 (&v)[8], char* hi, char* lo, int tid) {
    #pragma unroll
    for (int i = 0; i < 8; i++) {
        const int u = tid + i * 256;
        const int r = u >> 4, c4 = (u & 15) << 2;
        uint2 hv, lv; cvt_split(v[i], hv, lv);
        *(uint2*)((__nv_bfloat16*)hi + r * SPAD2 + c4) = hv;
        *(uint2*)((__nv_bfloat16*)lo + r * SPAD2 + c4) = lv;
    }
}

// One K-chunk of split-bf16 3-pass MMA (AhBh + AhBl + AlBh).
template <int MT, int NT, int STRIDE, int KC>
__device__ __forceinline__ void block_mma(
    const __nv_bfloat16* sAh, const __nv_bfloat16* sAl,
    const __nv_bfloat16* sBh, const __nv_bfloat16* sBl,
    int a_row0, int b_row0, int lane, float (&acc)[MT][NT][4]) {
    #pragma unroll
    for (int kb = 0; kb < KC; kb += 16) {
        uint32_t ah[MT][4], al[MT][4], bh[NT][2], bl[NT][2];
        const int ar = a_row0 + (lane & 15);
        const int ac = kb + ((lane >> 4) << 3);
        #pragma unroll
        for (int i = 0; i < MT; i++) {
            LDSM_X4(ah[i], s32(sAh + (ar + i * 16) * STRIDE + ac));
            LDSM_X4(al[i], s32(sAl + (ar + i * 16) * STRIDE + ac));
        }
        const int br = b_row0 + (lane & 7);
        const int bc = kb + (((lane >> 3) & 1) << 3);
        #pragma unroll
        for (int j = 0; j < NT; j++) {
            LDSM_X2(bh[j], s32(sBh + (br + j * 8) * STRIDE + bc));
            LDSM_X2(bl[j], s32(sBl + (br + j * 8) * STRIDE + bc));
        }
        #pragma unroll
        for (int i = 0; i < MT; i++)
            #pragma unroll
            for (int j = 0; j < NT; j++) {
                mma_bf16(acc[i][j], ah[i], bh[j]);
                mma_bf16(acc[i][j], ah[i], bl[j]);
                mma_bf16(acc[i][j], al[i], bh[j]);
            }
    }
}

// Stage a 32-col accumulator group into fp32 smem [128][33] (proj epilogue only).
template <int MT, int NT>
__device__ __forceinline__ void stage_group(float* stg, int warp_m, int col_base, int lane,
                                            float (&acc)[MT][NT][4], float scale) {
    const int r0 = warp_m * MT * 16 + (lane >> 2);
    const int c0 = (lane & 3) * 2;
    #pragma unroll
    for (int i = 0; i < MT; i++)
        #pragma unroll
        for (int j = 0; j < NT; j++) {
            float* p = stg + (size_t)(r0 + i * 16) * 33 + col_base + j * 8 + c0;
            p[0] = acc[i][j][0] * scale;
            p[1] = acc[i][j][1] * scale;
            p[8 * 33 + 0] = acc[i][j][2] * scale;
            p[8 * 33 + 1] = acc[i][j][3] * scale;
        }
}

// shared proj mainloop body: computes acc for (m0, n0) over A,W
__device__ __forceinline__ void proj_mainloop(
    const float* __restrict__ Ab, const float* __restrict__ Wb,
    char* sm, int tid, int lane, int warp_m, int warp_n, float (&acc)[4][2][4]) {
    float4 ra[4], rb[2];
    ldg_chunk<4>(ra, Ab, DD, tid);
    ldg_chunk<2>(rb, Wb, DD, tid);
    {
        char* s0 = sm;
        sts_chunk<4>(ra, (__nv_bfloat16*)(s0 + ST_AH), (__nv_bfloat16*)(s0 + ST_AL), tid);
        sts_chunk<2>(rb, (__nv_bfloat16*)(s0 + ST_BH), (__nv_bfloat16*)(s0 + ST_BL), tid);
    }
    ldg_chunk<4>(ra, Ab + 32, DD, tid);
    ldg_chunk<2>(rb, Wb + 32, DD, tid);
    __syncthreads();

    const int NK = DD / 32;   // 32
    for (int k = 0; k < NK; k++) {
        char* cur = sm + (k & 1) * STAGE_BYTES;
        block_mma<4, 2, SPAD, 32>((__nv_bfloat16*)(cur + ST_AH), (__nv_bfloat16*)(cur + ST_AL),
                                  (__nv_bfloat16*)(cur + ST_BH), (__nv_bfloat16*)(cur + ST_BL),
                                  warp_m * 64, warp_n * 16, lane, acc);
        if (k + 1 < NK) {
            char* nxt = sm + ((k + 1) & 1) * STAGE_BYTES;
            sts_chunk<4>(ra, (__nv_bfloat16*)(nxt + ST_AH), (__nv_bfloat16*)(nxt + ST_AL), tid);
            sts_chunk<2>(rb, (__nv_bfloat16*)(nxt + ST_BH), (__nv_bfloat16*)(nxt + ST_BL), tid);
        }
        if (k + 2 < NK) {
            ldg_chunk<4>(ra, Ab + (k + 2) * 32, DD, tid);
            ldg_chunk<2>(rb, Wb + (k + 2) * 32, DD, tid);
        }
        __syncthreads();
    }
}

// ===== fused Q/K/V projection: one launch, grid.z in {0:Q, 1:K, 2:V^T} =====
__global__ void __launch_bounds__(256, 2)
qkv_proj(const float* __restrict__ x,
         const float* __restrict__ Wq, const float* __restrict__ bq,
         const float* __restrict__ Wk, const float* __restrict__ bk,
         const float* __restrict__ Wv, const float* __restrict__ bv,
         float* __restrict__ q, float* __restrict__ k, float* __restrict__ vt) {
    extern __shared__ char sm[];
    const int tid = threadIdx.x, lane = tid & 31, wid = tid >> 5;
    const int warp_m = wid & 1, warp_n = wid >> 1;
    const int m0 = blockIdx.y * 128, n0 = blockIdx.x * 64;
    const int z = blockIdx.z;

    const float* W    = (z == 0) ? Wq : (z == 1) ? Wk : Wv;
    const float* bias = (z == 0) ? bq : (z == 1) ? bk : bv;

    float acc[4][2][4] = {};
    proj_mainloop(x + (size_t)m0 * DD, W + (size_t)n0 * DD, sm, tid, lane, warp_m, warp_n, acc);

    float* stg = (float*)sm;
    const int b = m0 >> 11, l0 = m0 & (LL - 1);
    for (int g = 0; g < 2; g++) {
        if ((warp_n >> 1) == g)
            stage_group<4, 2>(stg, warp_m, (warp_n & 1) * 16, lane, acc, 1.0f);
        __syncthreads();
        const int n_base = n0 + g * 32;
        const int h = n_base >> 6, cc = n_base & 63;
        if (z == 2) {
            float* dst = vt + ((size_t)(b * HH + h) * DKK + cc) * LL + l0;
            for (int u = tid; u < 1024; u += 256) {
                const int c = u >> 5, l4 = (u & 31) << 2;
                const float bv4 = bias[n_base + c];
                float4 v;
                v.x = stg[(size_t)(l4 + 0) * 33 + c] + bv4;
                v.y = stg[(size_t)(l4 + 1) * 33 + c] + bv4;
                v.z = stg[(size_t)(l4 + 2) * 33 + c] + bv4;
                v.w = stg[(size_t)(l4 + 3) * 33 + c] + bv4;
                *(float4*)(dst + (size_t)c * LL + l4) = v;
            }
        } else {
            float* outp = (z == 0) ? q : k;
            for (int u = tid; u < 1024; u += 256) {
                const int r = u >> 3, c4 = (u & 7) << 2;
                float4 v;
                v.x = stg[(size_t)r * 33 + c4 + 0] + bias[n_base + c4 + 0];
                v.y = stg[(size_t)r * 33 + c4 + 1] + bias[n_base + c4 + 1];
                v.z = stg[(size_t)r * 33 + c4 + 2] + bias[n_base + c4 + 2];
                v.w = stg[(size_t)r * 33 + c4 + 3] + bias[n_base + c4 + 3];
                *(float4*)(outp + ((size_t)(b * HH + h) * LL + l0 + r) * DKK + (cc + c4)) = v;
            }
        }
        __syncthreads();
    }
}

// ===== O projection (flat fp32 out) =====
__global__ void __launch_bounds__(256, 2)
gemm_projO(const float* __restrict__ A, const float* __restrict__ W,
           const float* __restrict__ bias, float* __restrict__ out) {
    extern __shared__ char sm[];
    const int tid = threadIdx.x, lane = tid & 31, wid = tid >> 5;
    const int warp_m = wid & 1, warp_n = wid >> 1;
    const int m0 = blockIdx.y * 128, n0 = blockIdx.x * 64;

    float acc[4][2][4] = {};
    proj_mainloop(A + (size_t)m0 * DD, W + (size_t)n0 * DD, sm, tid, lane, warp_m, warp_n, acc);

    float* stg = (float*)sm;
    for (int g = 0; g < 2; g++) {
        if ((warp_n >> 1) == g)
            stage_group<4, 2>(stg, warp_m, (warp_n & 1) * 16, lane, acc, 1.0f);
        __syncthreads();
        const int n_base = n0 + g * 32;
        for (int u = tid; u < 1024; u += 256) {
            const int r = u >> 3, c4 = (u & 7) << 2;
            float4 v;
            v.x = stg[(size_t)r * 33 + c4 + 0] + bias[n_base + c4 + 0];
            v.y = stg[(size_t)r * 33 + c4 + 1] + bias[n_base + c4 + 1];
            v.z = stg[(size_t)r * 33 + c4 + 2] + bias[n_base + c4 + 2];
            v.w = stg[(size_t)r * 33 + c4 + 3] + bias[n_base + c4 + 3];
            *(float4*)(out + (size_t)(m0 + r) * DD + n_base + c4) = v;
        }
        __syncthreads();
    }
}

// ===== scores: strips of 4 kt-tiles; Q loaded once; direct STG.64 epilogue =====
__global__ void __launch_bounds__(256, 2)
scores_mma(const float* __restrict__ q, const float* __restrict__ k,
           float* __restrict__ attn) {
    const int strip = blockIdx.x, qt = blockIdx.y, bhid = blockIdx.z;
    const int kt0 = strip * 4;
    const int q0 = qt * 128;
    extern __shared__ char sm[];
    const int tid = threadIdx.x, lane = tid & 31, wid = tid >> 5;
    const int warp_m = wid & 1, warp_n = wid >> 1;

    float* attnb = attn + ((size_t)bhid * LL + q0) * LL;

    if (kt0 > qt) {
        const float4 z = make_float4(0.f, 0.f, 0.f, 0.f);
        for (int u = tid; u < 128 * 128; u += 256) {
            const int r = u >> 7, c4 = (u & 127) << 2;
            *(float4*)(attnb + (size_t)r * LL + kt0 * 128 + c4) = z;
        }
        return;
    }

    load_split64((__nv_bfloat16*)(sm + SC_QH), (__nv_bfloat16*)(sm + SC_QL),
                 q + ((size_t)bhid * LL + q0) * DKK, DKK, tid);
    float4 kbuf[8];
    ldg_k(kbuf, k + ((size_t)bhid * LL + kt0 * 128) * DKK, tid);
    __syncthreads();

    const int rbase = warp_m * 64 + (lane >> 2);
    const int cbase = warp_n * 32 + (lane & 3) * 2;

    for (int kt = kt0; kt < kt0 + 4; kt++) {
        if (kt <= qt) {
            sts_k(kbuf, sm + SC_KH, sm + SC_KL, tid);
            __syncthreads();

            float acc[4][4][4] = {};
            block_mma<4, 4, SPAD2, 64>((__nv_bfloat16*)(sm + SC_QH), (__nv_bfloat16*)(sm + SC_QL),
                                       (__nv_bfloat16*)(sm + SC_KH), (__nv_bfloat16*)(sm + SC_KL),
                                       warp_m * 64, warp_n * 32, lane, acc);

            if (kt + 1 <= qt && kt + 1 < kt0 + 4)
                ldg_k(kbuf, k + ((size_t)bhid * LL + (kt + 1) * 128) * DKK, tid);

            #pragma unroll
            for (int i = 0; i < 4; i++)
                #pragma unroll
                for (int p = 0; p < 2; p++) {
                    const int r = rbase + i * 16 + p * 8;
                    float* rowp = attnb + (size_t)r * LL + kt * 128 + cbase;
                    #pragma unroll
                    for (int j = 0; j < 4; j++) {
                        float2 v = make_float2(acc[i][j][p * 2] * 0.125f,
                                               acc[i][j][p * 2 + 1] * 0.125f);
                        *(float2*)(rowp + j * 8) = v;
                    }
                }
            __syncthreads();
        } else {
            const float4 z = make_float4(0.f, 0.f, 0.f, 0.f);
            for (int u = tid; u < 128 * 32; u += 256) {
                const int r = u >> 5, c4 = (u & 31) << 2;
                *(float4*)(attnb + (size_t)r * LL + kt * 128 + c4) = z;
            }
        }
    }
}

// ================= row softmax (causal, bounded to qt-tile-aligned end) ============
__global__ void softmax_kernel(float* __restrict__ attn) {
    const int row = blockIdx.x, bh = blockIdx.y;
    float* p = attn + ((size_t)bh * LL + row) * LL;
    const int valid = row + 1;
    const int nend = (((row >> 7) + 1) << 7);
    const int tid = threadIdx.x;

    __shared__ float sred[8];

    float4 v[2];
    float m = -3.4e38f;
    #pragma unroll
    for (int i = 0; i < 2; i++) {
        const int j = (tid + i * 256) * 4;
        if (j < nend) {
            v[i] = *(const float4*)(p + j);
            if (j + 0 < valid) m = fmaxf(m, v[i].x);
            if (j + 1 < valid) m = fmaxf(m, v[i].y);
            if (j + 2 < valid) m = fmaxf(m, v[i].z);
            if (j + 3 < valid) m = fmaxf(m, v[i].w);
        }
    }
    #pragma unroll
    for (int o = 16; o > 0; o >>= 1) m = fmaxf(m, __shfl_xor_sync(0xffffffff, m, o));
    if ((tid & 31) == 0) sred[tid >> 5] = m;
    __syncthreads();
    m = sred[0];
    #pragma unroll
    for (int w = 1; w < 8; w++) m = fmaxf(m, sred[w]);

    float sum = 0.0f;
    #pragma unroll
    for (int i = 0; i < 2; i++) {
        const int j = (tid + i * 256) * 4;
        if (j < nend) {
            v[i].x = (j + 0 < valid) ? __expf(v[i].x - m) : 0.0f;
            v[i].y = (j + 1 < valid) ? __expf(v[i].y - m) : 0.0f;
            v[i].z = (j + 2 < valid) ? __expf(v[i].z - m) : 0.0f;
            v[i].w = (j + 3 < valid) ? __expf(v[i].w - m) : 0.0f;
            sum += v[i].x + v[i].y + v[i].z + v[i].w;
        }
    }
    __syncthreads();
    #pragma unroll
    for (int o = 16; o > 0; o >>= 1) sum += __shfl_xor_sync(0xffffffff, sum, o);
    if ((tid & 31) == 0) sred[tid >> 5] = sum;
    __syncthreads();
    sum = 0.0f;
    #pragma unroll
    for (int w = 0; w < 8; w++) sum += sred[w];
    const float inv = 1.0f / sum;

    #pragma unroll
    for (int i = 0; i < 2; i++) {
        const int j = (tid + i * 256) * 4;
        if (j < nend) {
            float4 o4;
            o4.x = v[i].x * inv; o4.y = v[i].y * inv;
            o4.z = v[i].z * inv; o4.w = v[i].w * inv;
            *(float4*)(p + j) = o4;
        }
    }
}

// ================= O = P @ V (causal k-range, pipelined, direct epilogue) ==========
__global__ void __launch_bounds__(256, 2)
av_mma(const float* __restrict__ attn, const float* __restrict__ vt,
       float* __restrict__ oc) {
    const int qt = blockIdx.x, bhid = blockIdx.y;
    const int b = bhid >> 4, h = bhid & 15;
    extern __shared__ char sm[];
    const int tid = threadIdx.x, lane = tid & 31, wid = tid >> 5;
    const int warp_m = wid & 1, warp_n = wid >> 1;
    const int q0 = qt * 128;

    const float* Pb = attn + ((size_t)bhid * LL + q0) * LL;
    const float* Vb = vt + (size_t)bhid * DKK * LL;

    float acc[4][2][4] = {};
    float4 ra[4], rb[2];

    const int NK = (qt + 1) * 4;

    ldg_chunk<4>(ra, Pb, LL, tid);
    ldg_chunk<2>(rb, Vb, LL, tid);
    {
        char* s0 = sm;
        sts_chunk<4>(ra, (__nv_bfloat16*)(s0 + ST_AH), (__nv_bfloat16*)(s0 + ST_AL), tid);
        sts_chunk<2>(rb, (__nv_bfloat16*)(s0 + ST_BH), (__nv_bfloat16*)(s0 + ST_BL), tid);
    }
    ldg_chunk<4>(ra, Pb + 32, LL, tid);
    ldg_chunk<2>(rb, Vb + 32, LL, tid);
    __syncthreads();

    for (int k = 0; k < NK; k++) {
        char* cur = sm + (k & 1) * STAGE_BYTES;
        block_mma<4, 2, SPAD, 32>((__nv_bfloat16*)(cur + ST_AH), (__nv_bfloat16*)(cur + ST_AL),
                                  (__nv_bfloat16*)(cur + ST_BH), (__nv_bfloat16*)(cur + ST_BL),
                                  warp_m * 64, warp_n * 16, lane, acc);
        if (k + 1 < NK) {
            char* nxt = sm + ((k + 1) & 1) * STAGE_BYTES;
            sts_chunk<4>(ra, (__nv_bfloat16*)(nxt + ST_AH), (__nv_bfloat16*)(nxt + ST_AL), tid);
            sts_chunk<2>(rb, (__nv_bfloat16*)(nxt + ST_BH), (__nv_bfloat16*)(nxt + ST_BL), tid);
        }
        if (k + 2 < NK) {
            ldg_chunk<4>(ra, Pb + (k + 2) * 32, LL, tid);
            ldg_chunk<2>(rb, Vb + (k + 2) * 32, LL, tid);
        }
        __syncthreads();
    }

    const int rbase = warp_m * 64 + (lane >> 2);
    const int cbase = warp_n * 16 + (lane & 3) * 2;
    #pragma unroll
    for (int i = 0; i < 4; i++)
        #pragma unroll
        for (int p = 0; p < 2; p++) {
            const int r = rbase + i * 16 + p * 8;
            float* rowp = oc + (size_t)(b * LL + q0 + r) * DD + h * DKK + cbase;
            #pragma unroll
            for (int j = 0; j < 2; j++) {
                float2 v = make_float2(acc[i][j][p * 2], acc[i][j][p * 2 + 1]);
                *(float2*)(rowp + j * 8) = v;
            }
        }
}

// ---------------- launch ----------------
extern "C" void kernel_launch(void* const* d_in, const int* in_sizes, int n_in,
                              void* d_out, int out_size) {
    const float* x  = (const float*)d_in[0];
    const float* Wq = (const float*)d_in[2];
    const float* bq = (const float*)d_in[3];
    const float* Wk = (const float*)d_in[4];
    const float* bk = (const float*)d_in[5];
    const float* Wv = (const float*)d_in[6];
    const float* bv = (const float*)d_in[7];
    const float* Wo = (const float*)d_in[8];
    const float* bo = (const float*)d_in[9];
    float* out = (float*)d_out;

    const size_t out_elems  = (size_t)BB * LL * DD;
    const size_t attn_elems = (size_t)BH * LL * LL;

    float *q, *k, *vt, *oc, *attn;
    cudaGetSymbolAddress((void**)&q,  g_q);
    cudaGetSymbolAddress((void**)&k,  g_k);
    cudaGetSymbolAddress((void**)&vt, g_vt);
    cudaGetSymbolAddress((void**)&oc, g_oc);
    if ((size_t)out_size >= out_elems + attn_elems) {
        attn = out + out_elems;
    } else {
        cudaGetSymbolAddress((void**)&attn, g_attn_scratch);
    }

    cudaFuncSetAttribute(qkv_proj,   cudaFuncAttributeMaxDynamicSharedMemorySize, PIPE_SMEM);
    cudaFuncSetAttribute(gemm_projO, cudaFuncAttributeMaxDynamicSharedMemorySize, PIPE_SMEM);
    cudaFuncSetAttribute(scores_mma, cudaFuncAttributeMaxDynamicSharedMemorySize, SC_SMEM);
    cudaFuncSetAttribute(av_mma,     cudaFuncAttributeMaxDynamicSharedMemorySize, PIPE_SMEM);

    dim3 qkvGrid(DD / 64, MROWS / 128, 3);     // (16, 64, 3) = 3072 blocks, one launch
    qkv_proj<<<qkvGrid, 256, PIPE_SMEM>>>(x, Wq, bq, Wk, bk, Wv, bv, q, k, vt);

    dim3 scoreGrid(4, LL / 128, BH);           // (4, 16, 64)
    scores_mma<<<scoreGrid, 256, SC_SMEM>>>(q, k, attn);

    dim3 smGrid(LL, BH);
    softmax_kernel<<<smGrid, 256>>>(attn);

    dim3 avGrid(LL / 128, BH);                 // (16, 64)
    av_mma<<<avGrid, 256, PIPE_SMEM>>>(attn, vt, oc);

    dim3 projGrid(DD / 64, MROWS / 128);       // (16, 64)
    gemm_projO<<<projGrid, 256, PIPE_SMEM>>>(oc, Wo, bo, out);
}

// round 17
// speedup vs baseline: 1.0980x; 1.0641x over previous
#include <cuda_runtime.h>
#include <cuda_bf16.h>
#include <cstdint>
#include <math.h>

#define BB 4
#define LL 2048
#define DD 1024
#define HH 16
#define DKK 64
#define BH (BB*HH)        // 64
#define MROWS (BB*LL)     // 8192

#define SPAD 40           // smem row stride (bf16) for K=32 chunks
#define SPAD2 72          // smem row stride (bf16) for K=64 tiles (scores)

#define ST_AH 0
#define ST_AL 10240       // 128*40*2
#define ST_BH 20480
#define ST_BL 25600       // 64*40*2
#define STAGE_BYTES 30720
#define PIPE_SMEM (2*STAGE_BYTES)      // 61440

#define SC_QH 0
#define SC_QL 18432       // 128*72*2
#define SC_KH 36864
#define SC_KL 55296
#define SC_SMEM 73728

__device__ float g_q[(size_t)BH * LL * DKK];
__device__ float g_k[(size_t)BH * LL * DKK];
__device__ float g_vt[(size_t)BH * DKK * LL];
__device__ float g_oc[(size_t)MROWS * DD];
__device__ float g_attn_scratch[(size_t)BH * LL * LL];

__device__ __forceinline__ uint32_t s32(const void* p) {
    return (uint32_t)__cvta_generic_to_shared(p);
}

#define LDSM_X4(R, a)                                                          \
    asm volatile("ldmatrix.sync.aligned.m8n8.x4.shared.b16 {%0,%1,%2,%3}, [%4];" \
        : "=r"((R)[0]), "=r"((R)[1]), "=r"((R)[2]), "=r"((R)[3]) : "r"(a))
#define LDSM_X2(R, a)                                                          \
    asm volatile("ldmatrix.sync.aligned.m8n8.x2.shared.b16 {%0,%1}, [%2];"     \
        : "=r"((R)[0]), "=r"((R)[1]) : "r"(a))

__device__ __forceinline__ void mma_bf16(float* c, const uint32_t* a, const uint32_t* b) {
    asm volatile(
        "mma.sync.aligned.m16n8k16.row.col.f32.bf16.bf16.f32 "
        "{%0,%1,%2,%3}, {%4,%5,%6,%7}, {%8,%9}, {%0,%1,%2,%3};"
        : "+f"(c[0]), "+f"(c[1]), "+f"(c[2]), "+f"(c[3])
        : "r"(a[0]), "r"(a[1]), "r"(a[2]), "r"(a[3]), "r"(b[0]), "r"(b[1]));
}

__device__ __forceinline__ void cvt_split(const float4& v, uint2& hv, uint2& lv) {
    __nv_bfloat16 h0 = __float2bfloat16(v.x), h1 = __float2bfloat16(v.y);
    __nv_bfloat16 h2 = __float2bfloat16(v.z), h3 = __float2bfloat16(v.w);
    __nv_bfloat16 l0 = __float2bfloat16(v.x - __bfloat162float(h0));
    __nv_bfloat16 l1 = __float2bfloat16(v.y - __bfloat162float(h1));
    __nv_bfloat16 l2 = __float2bfloat16(v.z - __bfloat162float(h2));
    __nv_bfloat16 l3 = __float2bfloat16(v.w - __bfloat162float(h3));
    hv.x = ((uint32_t)__bfloat16_as_ushort(h1) << 16) | __bfloat16_as_ushort(h0);
    hv.y = ((uint32_t)__bfloat16_as_ushort(h3) << 16) | __bfloat16_as_ushort(h2);
    lv.x = ((uint32_t)__bfloat16_as_ushort(l1) << 16) | __bfloat16_as_ushort(l0);
    lv.y = ((uint32_t)__bfloat16_as_ushort(l3) << 16) | __bfloat16_as_ushort(l2);
}

template <int N4>
__device__ __forceinline__ void ldg_chunk(float4 (&r)[N4], const float* __restrict__ g,
                                          int ld, int tid) {
    #pragma unroll
    for (int i = 0; i < N4; i++) {
        const int u = tid + i * 256;
        const int row = u >> 3, c4 = (u & 7) << 2;
        r[i] = *(const float4*)(g + (size_t)row * ld + c4);
    }
}
template <int N4>
__device__ __forceinline__ void sts_chunk(const float4 (&v)[N4], __nv_bfloat16* shi,
                                          __nv_bfloat16* slo, int tid) {
    #pragma unroll
    for (int i = 0; i < N4; i++) {
        const int u = tid + i * 256;
        const int row = u >> 3, c4 = (u & 7) << 2;
        uint2 hv, lv; cvt_split(v[i], hv, lv);
        *(uint2*)(shi + row * SPAD + c4) = hv;
        *(uint2*)(slo + row * SPAD + c4) = lv;
    }
}

__device__ __forceinline__ void load_split64(__nv_bfloat16* shi, __nv_bfloat16* slo,
                                             const float* __restrict__ g, int ld, int tid) {
    #pragma unroll
    for (int i = 0; i < 8; i++) {
        const int u = tid + i * 256;
        const int r = u >> 4, c4 = (u & 15) << 2;
        float4 v = *(const float4*)(g + (size_t)r * ld + c4);
        uint2 hv, lv; cvt_split(v, hv, lv);
        *(uint2*)(shi + r * SPAD2 + c4) = hv;
        *(uint2*)(slo + r * SPAD2 + c4) = lv;
    }
}

__device__ __forceinline__ void ldg_k(float4 (&r)[8], const float* __restrict__ g, int tid) {
    #pragma unroll
    for (int i = 0; i < 8; i++) {
        const int u = tid + i * 256;
        r[i] = *(const float4*)(g + (size_t)(u >> 4) * DKK + ((u & 15) << 2));
    }
}
__device__ __forceinline__ void sts_k(const float4 (&v)[8], char* hi, char* lo, int tid) {
    #pragma unroll
    for (int i = 0; i < 8; i++) {
        const int u = tid + i * 256;
        const int r = u >> 4, c4 = (u & 15) << 2;
        uint2 hv, lv; cvt_split(v[i], hv, lv);
        *(uint2*)((__nv_bfloat16*)hi + r * SPAD2 + c4) = hv;
        *(uint2*)((__nv_bfloat16*)lo + r * SPAD2 + c4) = lv;
    }
}

template <int MT, int NT, int STRIDE, int KC>
__device__ __forceinline__ void block_mma(
    const __nv_bfloat16* sAh, const __nv_bfloat16* sAl,
    const __nv_bfloat16* sBh, const __nv_bfloat16* sBl,
    int a_row0, int b_row0, int lane, float (&acc)[MT][NT][4]) {
    #pragma unroll
    for (int kb = 0; kb < KC; kb += 16) {
        uint32_t ah[MT][4], al[MT][4], bh[NT][2], bl[NT][2];
        const int ar = a_row0 + (lane & 15);
        const int ac = kb + ((lane >> 4) << 3);
        #pragma unroll
        for (int i = 0; i < MT; i++) {
            LDSM_X4(ah[i], s32(sAh + (ar + i * 16) * STRIDE + ac));
            LDSM_X4(al[i], s32(sAl + (ar + i * 16) * STRIDE + ac));
        }
        const int br = b_row0 + (lane & 7);
        const int bc = kb + (((lane >> 3) & 1) << 3);
        #pragma unroll
        for (int j = 0; j < NT; j++) {
            LDSM_X2(bh[j], s32(sBh + (br + j * 8) * STRIDE + bc));
            LDSM_X2(bl[j], s32(sBl + (br + j * 8) * STRIDE + bc));
        }
        #pragma unroll
        for (int i = 0; i < MT; i++)
            #pragma unroll
            for (int j = 0; j < NT; j++) {
                mma_bf16(acc[i][j], ah[i], bh[j]);
                mma_bf16(acc[i][j], ah[i], bl[j]);
                mma_bf16(acc[i][j], al[i], bh[j]);
            }
    }
}

template <int MT, int NT>
__device__ __forceinline__ void stage_group(float* stg, int warp_m, int col_base, int lane,
                                            float (&acc)[MT][NT][4], float scale) {
    const int r0 = warp_m * MT * 16 + (lane >> 2);
    const int c0 = (lane & 3) * 2;
    #pragma unroll
    for (int i = 0; i < MT; i++)
        #pragma unroll
        for (int j = 0; j < NT; j++) {
            float* p = stg + (size_t)(r0 + i * 16) * 33 + col_base + j * 8 + c0;
            p[0] = acc[i][j][0] * scale;
            p[1] = acc[i][j][1] * scale;
            p[8 * 33 + 0] = acc[i][j][2] * scale;
            p[8 * 33 + 1] = acc[i][j][3] * scale;
        }
}

// shared proj mainloop body (warp tile 32x32)
__device__ __forceinline__ void proj_mainloop(
    const float* __restrict__ Ab, const float* __restrict__ Wb,
    char* sm, int tid, int lane, int warp_m, int warp_n, float (&acc)[2][4][4]) {
    float4 ra[4], rb[2];
    ldg_chunk<4>(ra, Ab, DD, tid);
    ldg_chunk<2>(rb, Wb, DD, tid);
    {
        char* s0 = sm;
        sts_chunk<4>(ra, (__nv_bfloat16*)(s0 + ST_AH), (__nv_bfloat16*)(s0 + ST_AL), tid);
        sts_chunk<2>(rb, (__nv_bfloat16*)(s0 + ST_BH), (__nv_bfloat16*)(s0 + ST_BL), tid);
    }
    ldg_chunk<4>(ra, Ab + 32, DD, tid);
    ldg_chunk<2>(rb, Wb + 32, DD, tid);
    __syncthreads();

    const int NK = DD / 32;
    for (int k = 0; k < NK; k++) {
        char* cur = sm + (k & 1) * STAGE_BYTES;
        block_mma<2, 4, SPAD, 32>((__nv_bfloat16*)(cur + ST_AH), (__nv_bfloat16*)(cur + ST_AL),
                                  (__nv_bfloat16*)(cur + ST_BH), (__nv_bfloat16*)(cur + ST_BL),
                                  warp_m * 32, warp_n * 32, lane, acc);
        if (k + 1 < NK) {
            char* nxt = sm + ((k + 1) & 1) * STAGE_BYTES;
            sts_chunk<4>(ra, (__nv_bfloat16*)(nxt + ST_AH), (__nv_bfloat16*)(nxt + ST_AL), tid);
            sts_chunk<2>(rb, (__nv_bfloat16*)(nxt + ST_BH), (__nv_bfloat16*)(nxt + ST_BL), tid);
        }
        if (k + 2 < NK) {
            ldg_chunk<4>(ra, Ab + (k + 2) * 32, DD, tid);
            ldg_chunk<2>(rb, Wb + (k + 2) * 32, DD, tid);
        }
        __syncthreads();
    }
}

__global__ void __launch_bounds__(256, 2)
qkv_proj(const float* __restrict__ x,
         const float* __restrict__ Wq, const float* __restrict__ bq,
         const float* __restrict__ Wk, const float* __restrict__ bk,
         const float* __restrict__ Wv, const float* __restrict__ bv,
         float* __restrict__ q, float* __restrict__ k, float* __restrict__ vt) {
    extern __shared__ char sm[];
    const int tid = threadIdx.x, lane = tid & 31, wid = tid >> 5;
    const int warp_m = wid & 3, warp_n = wid >> 2;   // 4 x 2; warp tile 32x32
    const int m0 = blockIdx.y * 128, n0 = blockIdx.x * 64;
    const int z = blockIdx.z;

    const float* W    = (z == 0) ? Wq : (z == 1) ? Wk : Wv;
    const float* bias = (z == 0) ? bq : (z == 1) ? bk : bv;

    float acc[2][4][4] = {};
    proj_mainloop(x + (size_t)m0 * DD, W + (size_t)n0 * DD, sm, tid, lane, warp_m, warp_n, acc);

    float* stg = (float*)sm;
    const int b = m0 >> 11, l0 = m0 & (LL - 1);
    for (int g = 0; g < 2; g++) {
        if (warp_n == g)
            stage_group<2, 4>(stg, warp_m, 0, lane, acc, 1.0f);
        __syncthreads();
        const int n_base = n0 + g * 32;
        const int h = n_base >> 6, cc = n_base & 63;
        if (z == 2) {
            float* dst = vt + ((size_t)(b * HH + h) * DKK + cc) * LL + l0;
            for (int u = tid; u < 1024; u += 256) {
                const int c = u >> 5, l4 = (u & 31) << 2;
                const float bv4 = bias[n_base + c];
                float4 v;
                v.x = stg[(size_t)(l4 + 0) * 33 + c] + bv4;
                v.y = stg[(size_t)(l4 + 1) * 33 + c] + bv4;
                v.z = stg[(size_t)(l4 + 2) * 33 + c] + bv4;
                v.w = stg[(size_t)(l4 + 3) * 33 + c] + bv4;
                *(float4*)(dst + (size_t)c * LL + l4) = v;
            }
        } else {
            float* outp = (z == 0) ? q : k;
            for (int u = tid; u < 1024; u += 256) {
                const int r = u >> 3, c4 = (u & 7) << 2;
                float4 v;
                v.x = stg[(size_t)r * 33 + c4 + 0] + bias[n_base + c4 + 0];
                v.y = stg[(size_t)r * 33 + c4 + 1] + bias[n_base + c4 + 1];
                v.z = stg[(size_t)r * 33 + c4 + 2] + bias[n_base + c4 + 2];
                v.w = stg[(size_t)r * 33 + c4 + 3] + bias[n_base + c4 + 3];
                *(float4*)(outp + ((size_t)(b * HH + h) * LL + l0 + r) * DKK + (cc + c4)) = v;
            }
        }
        __syncthreads();
    }
}

__global__ void __launch_bounds__(256, 2)
gemm_projO(const float* __restrict__ A, const float* __restrict__ W,
           const float* __restrict__ bias, float* __restrict__ out) {
    extern __shared__ char sm[];
    const int tid = threadIdx.x, lane = tid & 31, wid = tid >> 5;
    const int warp_m = wid & 3, warp_n = wid >> 2;
    const int m0 = blockIdx.y * 128, n0 = blockIdx.x * 64;

    float acc[2][4][4] = {};
    proj_mainloop(A + (size_t)m0 * DD, W + (size_t)n0 * DD, sm, tid, lane, warp_m, warp_n, acc);

    float* stg = (float*)sm;
    for (int g = 0; g < 2; g++) {
        if (warp_n == g)
            stage_group<2, 4>(stg, warp_m, 0, lane, acc, 1.0f);
        __syncthreads();
        const int n_base = n0 + g * 32;
        for (int u = tid; u < 1024; u += 256) {
            const int r = u >> 3, c4 = (u & 7) << 2;
            float4 v;
            v.x = stg[(size_t)r * 33 + c4 + 0] + bias[n_base + c4 + 0];
            v.y = stg[(size_t)r * 33 + c4 + 1] + bias[n_base + c4 + 1];
            v.z = stg[(size_t)r * 33 + c4 + 2] + bias[n_base + c4 + 2];
            v.w = stg[(size_t)r * 33 + c4 + 3] + bias[n_base + c4 + 3];
            *(float4*)(out + (size_t)(m0 + r) * DD + n_base + c4) = v;
        }
        __syncthreads();
    }
}

__global__ void __launch_bounds__(256, 2)
scores_mma(const float* __restrict__ q, const float* __restrict__ k,
           float* __restrict__ attn) {
    const int strip = blockIdx.x, qt = blockIdx.y, bhid = blockIdx.z;
    const int kt0 = strip * 4;
    const int q0 = qt * 128;
    extern __shared__ char sm[];
    const int tid = threadIdx.x, lane = tid & 31, wid = tid >> 5;
    const int warp_m = wid & 1, warp_n = wid >> 1;

    float* attnb = attn + ((size_t)bhid * LL + q0) * LL;

    if (kt0 > qt) {
        const float4 z = make_float4(0.f, 0.f, 0.f, 0.f);
        for (int u = tid; u < 128 * 128; u += 256) {
            const int r = u >> 7, c4 = (u & 127) << 2;
            *(float4*)(attnb + (size_t)r * LL + kt0 * 128 + c4) = z;
        }
        return;
    }

    load_split64((__nv_bfloat16*)(sm + SC_QH), (__nv_bfloat16*)(sm + SC_QL),
                 q + ((size_t)bhid * LL + q0) * DKK, DKK, tid);
    float4 kbuf[8];
    ldg_k(kbuf, k + ((size_t)bhid * LL + kt0 * 128) * DKK, tid);
    __syncthreads();

    const int rbase = warp_m * 64 + (lane >> 2);
    const int cbase = warp_n * 32 + (lane & 3) * 2;

    for (int kt = kt0; kt < kt0 + 4; kt++) {
        if (kt <= qt) {
            sts_k(kbuf, sm + SC_KH, sm + SC_KL, tid);
            __syncthreads();

            float acc[4][4][4] = {};
            block_mma<4, 4, SPAD2, 64>((__nv_bfloat16*)(sm + SC_QH), (__nv_bfloat16*)(sm + SC_QL),
                                       (__nv_bfloat16*)(sm + SC_KH), (__nv_bfloat16*)(sm + SC_KL),
                                       warp_m * 64, warp_n * 32, lane, acc);

            if (kt + 1 <= qt && kt + 1 < kt0 + 4)
                ldg_k(kbuf, k + ((size_t)bhid * LL + (kt + 1) * 128) * DKK, tid);

            #pragma unroll
            for (int i = 0; i < 4; i++)
                #pragma unroll
                for (int p = 0; p < 2; p++) {
                    const int r = rbase + i * 16 + p * 8;
                    float* rowp = attnb + (size_t)r * LL + kt * 128 + cbase;
                    #pragma unroll
                    for (int j = 0; j < 4; j++) {
                        float2 v = make_float2(acc[i][j][p * 2] * 0.125f,
                                               acc[i][j][p * 2 + 1] * 0.125f);
                        *(float2*)(rowp + j * 8) = v;
                    }
                }
            __syncthreads();
        } else {
            const float4 z = make_float4(0.f, 0.f, 0.f, 0.f);
            for (int u = tid; u < 128 * 32; u += 256) {
                const int r = u >> 5, c4 = (u & 31) << 2;
                *(float4*)(attnb + (size_t)r * LL + kt * 128 + c4) = z;
            }
        }
    }
}

__global__ void softmax_kernel(float* __restrict__ attn) {
    const int row = blockIdx.x, bh = blockIdx.y;
    float* p = attn + ((size_t)bh * LL + row) * LL;
    const int valid = row + 1;
    const int nend = (((row >> 7) + 1) << 7);
    const int tid = threadIdx.x;

    __shared__ float sred[8];

    float4 v[2];
    float m = -3.4e38f;
    #pragma unroll
    for (int i = 0; i < 2; i++) {
        const int j = (tid + i * 256) * 4;
        if (j < nend) {
            v[i] = *(const float4*)(p + j);
            if (j + 0 < valid) m = fmaxf(m, v[i].x);
            if (j + 1 < valid) m = fmaxf(m, v[i].y);
            if (j + 2 < valid) m = fmaxf(m, v[i].z);
            if (j + 3 < valid) m = fmaxf(m, v[i].w);
        }
    }
    #pragma unroll
    for (int o = 16; o > 0; o >>= 1) m = fmaxf(m, __shfl_xor_sync(0xffffffff, m, o));
    if ((tid & 31) == 0) sred[tid >> 5] = m;
    __syncthreads();
    m = sred[0];
    #pragma unroll
    for (int w = 1; w < 8; w++) m = fmaxf(m, sred[w]);

    float sum = 0.0f;
    #pragma unroll
    for (int i = 0; i < 2; i++) {
        const int j = (tid + i * 256) * 4;
        if (j < nend) {
            v[i].x = (j + 0 < valid) ? __expf(v[i].x - m) : 0.0f;
            v[i].y = (j + 1 < valid) ? __expf(v[i].y - m) : 0.0f;
            v[i].z = (j + 2 < valid) ? __expf(v[i].z - m) : 0.0f;
            v[i].w = (j + 3 < valid) ? __expf(v[i].w - m) : 0.0f;
            sum += v[i].x + v[i].y + v[i].z + v[i].w;
        }
    }
    __syncthreads();
    #pragma unroll
    for (int o = 16; o > 0; o >>= 1) sum += __shfl_xor_sync(0xffffffff, sum, o);
    if ((tid & 31) == 0) sred[tid >> 5] = sum;
    __syncthreads();
    sum = 0.0f;
    #pragma unroll
    for (int w = 0; w < 8; w++) sum += sred[w];
    const float inv = 1.0f / sum;

    #pragma unroll
    for (int i = 0; i < 2; i++) {
        const int j = (tid + i * 256) * 4;
        if (j < nend) {
            float4 o4;
            o4.x = v[i].x * inv; o4.y = v[i].y * inv;
            o4.z = v[i].z * inv; o4.w = v[i].w * inv;
            *(float4*)(p + j) = o4;
        }
    }
}

__global__ void __launch_bounds__(256, 2)
av_mma(const float* __restrict__ attn, const float* __restrict__ vt,
       float* __restrict__ oc) {
    const int qt = (gridDim.x - 1) - blockIdx.x;   // heavy blocks first
    const int bhid = blockIdx.y;
    const int b = bhid >> 4, h = bhid & 15;
    extern __shared__ char sm[];
    const int tid = threadIdx.x, lane = tid & 31, wid = tid >> 5;
    const int warp_m = wid & 3, warp_n = wid >> 2;   // 4 x 2; warp tile 32x32
    const int q0 = qt * 128;

    const float* Pb = attn + ((size_t)bhid * LL + q0) * LL;
    const float* Vb = vt + (size_t)bhid * DKK * LL;

    float acc[2][4][4] = {};
    float4 ra[4], rb[2];

    const int NK = (qt + 1) * 4;

    ldg_chunk<4>(ra, Pb, LL, tid);
    ldg_chunk<2>(rb, Vb, LL, tid);
    {
        char* s0 = sm;
        sts_chunk<4>(ra, (__nv_bfloat16*)(s0 + ST_AH), (__nv_bfloat16*)(s0 + ST_AL), tid);
        sts_chunk<2>(rb, (__nv_bfloat16*)(s0 + ST_BH), (__nv_bfloat16*)(s0 + ST_BL), tid);
    }
    ldg_chunk<4>(ra, Pb + 32, LL, tid);
    ldg_chunk<2>(rb, Vb + 32, LL, tid);
    __syncthreads();

    for (int k = 0; k < NK; k++) {
        char* cur = sm + (k & 1) * STAGE_BYTES;
        block_mma<2, 4, SPAD, 32>((__nv_bfloat16*)(cur + ST_AH), (__nv_bfloat16*)(cur + ST_AL),
                                  (__nv_bfloat16*)(cur + ST_BH), (__nv_bfloat16*)(cur + ST_BL),
                                  warp_m * 32, warp_n * 32, lane, acc);
        if (k + 1 < NK) {
            char* nxt = sm + ((k + 1) & 1) * STAGE_BYTES;
            sts_chunk<4>(ra, (__nv_bfloat16*)(nxt + ST_AH), (__nv_bfloat16*)(nxt + ST_AL), tid);
            sts_chunk<2>(rb, (__nv_bfloat16*)(nxt + ST_BH), (__nv_bfloat16*)(nxt + ST_BL), tid);
        }
        if (k + 2 < NK) {
            ldg_chunk<4>(ra, Pb + (k + 2) * 32, LL, tid);
            ldg_chunk<2>(rb, Vb + (k + 2) * 32, LL, tid);
        }
        __syncthreads();
    }

    const int rbase = warp_m * 32 + (lane >> 2);
    const int cbase = warp_n * 32 + (lane & 3) * 2;
    #pragma unroll
    for (int i = 0; i < 2; i++)
        #pragma unroll
        for (int p = 0; p < 2; p++) {
            const int r = rbase + i * 16 + p * 8;
            float* rowp = oc + (size_t)(b * LL + q0 + r) * DD + h * DKK + cbase;
            #pragma unroll
            for (int j = 0; j < 4; j++) {
                float2 v = make_float2(acc[i][j][p * 2], acc[i][j][p * 2 + 1]);
                *(float2*)(rowp + j * 8) = v;
            }
        }
}

extern "C" void kernel_launch(void* const* d_in, const int* in_sizes, int n_in,
                              void* d_out, int out_size) {
    const float* x  = (const float*)d_in[0];
    const float* Wq = (const float*)d_in[2];
    const float* bq = (const float*)d_in[3];
    const float* Wk = (const float*)d_in[4];
    const float* bk = (const float*)d_in[5];
    const float* Wv = (const float*)d_in[6];
    const float* bv = (const float*)d_in[7];
    const float* Wo = (const float*)d_in[8];
    const float* bo = (const float*)d_in[9];
    float* out = (float*)d_out;

    const size_t out_elems  = (size_t)BB * LL * DD;
    const size_t attn_elems = (size_t)BH * LL * LL;

    float *q, *k, *vt, *oc, *attn;
    cudaGetSymbolAddress((void**)&q,  g_q);
    cudaGetSymbolAddress((void**)&k,  g_k);
    cudaGetSymbolAddress((void**)&vt, g_vt);
    cudaGetSymbolAddress((void**)&oc, g_oc);
    if ((size_t)out_size >= out_elems + attn_elems) {
        attn = out + out_elems;
    } else {
        cudaGetSymbolAddress((void**)&attn, g_attn_scratch);
    }

    cudaFuncSetAttribute(qkv_proj,   cudaFuncAttributeMaxDynamicSharedMemorySize, PIPE_SMEM);
    cudaFuncSetAttribute(gemm_projO, cudaFuncAttributeMaxDynamicSharedMemorySize, PIPE_SMEM);
    cudaFuncSetAttribute(scores_mma, cudaFuncAttributeMaxDynamicSharedMemorySize, SC_SMEM);
    cudaFuncSetAttribute(av_mma,     cudaFuncAttributeMaxDynamicSharedMemorySize, PIPE_SMEM);

    dim3 qkvGrid(DD / 64, MROWS / 128, 3);
    qkv_proj<<<qkvGrid, 256, PIPE_SMEM>>>(x, Wq, bq, Wk, bk, Wv, bv, q, k, vt);

    dim3 scoreGrid(4, LL / 128, BH);
    scores_mma<<<scoreGrid, 256, SC_SMEM>>>(q, k, attn);

    dim3 smGrid(LL, BH);
    softmax_kernel<<<smGrid, 256>>>(attn);

    dim3 avGrid(LL / 128, BH);
    av_mma<<<avGrid, 256, PIPE_SMEM>>>(attn, vt, oc);

    dim3 projGrid(DD / 64, MROWS / 128);
    gemm_projO<<<projGrid, 256, PIPE_SMEM>>>(oc, Wo, bo, out);
}